// round 5
// baseline (speedup 1.0000x reference)
#include <cuda_runtime.h>
#include <cuda_bf16.h>
#include <cstdint>

#define NEG_INIT -1.0e9f

// ---------------------------------------------------------------------------
__device__ __forceinline__ unsigned enc_f(float f) {
    unsigned u = __float_as_uint(f);
    return (u & 0x80000000u) ? ~u : (u | 0x80000000u);
}
__device__ __forceinline__ float dec_f(unsigned e) {
    unsigned u = (e & 0x80000000u) ? (e & 0x7FFFFFFFu) : ~e;
    return __uint_as_float(u);
}
__device__ __forceinline__ float lrelu(float x) { return x >= 0.f ? x : 0.2f * x; }

__device__ unsigned g_gf[16384 * 128];   // encoded global_feats scratch (8 MB)

__device__ __forceinline__ uint32_t smem_u32(const void* p) {
    uint32_t a;
    asm("{ .reg .u64 t; cvta.to.shared.u64 t, %1; cvt.u32.u64 %0, t; }" : "=r"(a) : "l"(p));
    return a;
}

__device__ __forceinline__ void ldsm4(unsigned r[4], uint32_t addr) {
    asm volatile("ldmatrix.sync.aligned.m8n8.x4.shared.b16 {%0,%1,%2,%3}, [%4];"
                 : "=r"(r[0]), "=r"(r[1]), "=r"(r[2]), "=r"(r[3]) : "r"(addr));
}
__device__ __forceinline__ void imma(int d[4], const unsigned a[4],
                                     unsigned b0, unsigned b1) {
    asm volatile(
        "mma.sync.aligned.m16n8k32.row.col.s32.s8.s8.s32 "
        "{%0,%1,%2,%3}, {%4,%5,%6,%7}, {%8,%9}, {%0,%1,%2,%3};"
        : "+r"(d[0]), "+r"(d[1]), "+r"(d[2]), "+r"(d[3])
        : "r"(a[0]), "r"(a[1]), "r"(a[2]), "r"(a[3]), "r"(b0), "r"(b1));
}
__device__ __forceinline__ unsigned pack4_s8(int x0, int x1, int x2, int x3) {
    unsigned tmp, d; int z = 0;
    asm("cvt.pack.sat.s8.s32.b32 %0, %1, %2, %3;" : "=r"(tmp) : "r"(x3), "r"(x2), "r"(z));
    asm("cvt.pack.sat.s8.s32.b32 %0, %1, %2, %3;" : "=r"(d)   : "r"(x1), "r"(x0), "r"(tmp));
    return d;
}

// ---------------------------------------------------------------------------
// SMEM layout (bytes).  A8/B8 rows: 128 B = [64B digit-1 | 64B digit-2],
// swizzled in 16B chunks: phys_chunk = chunk ^ (row & 7).
// ---------------------------------------------------------------------------
#define OFF_B8    0          // 128 x 128 int8
#define OFF_A8    16384      // 128 x 128 int8
#define OFF_W1    32768      // 448 floats
#define OFF_B1    34560      // 64 floats
#define OFF_B2    34816      // 128 floats
#define OFF_BIDX  35328      // 128 ints
#define OFF_COND  35840      // 128*4 floats
#define OFF_FM    37888      // 128*3 floats
#define OFF_PMAX  39424      // 256 floats
#define OFF_SA    40448      // 128 floats
#define OFF_TB    40960      // 128 floats
#define SMEM_BYTES 41472

// ---------------------------------------------------------------------------
__global__ void init_gf_kernel(int total4) {
    int i = blockIdx.x * blockDim.x + threadIdx.x;
    if (i < total4) {
        unsigned e = enc_f(NEG_INIT);
        ((uint4*)g_gf)[i] = make_uint4(e, e, e, e);
    }
}

// ---------------------------------------------------------------------------
// Persistent fused point kernel: layer1 (FFMA) + layer2 (IMMA s8 two-digit)
// + in-register segmented max.  256 threads, grid = 296.
// ---------------------------------------------------------------------------
__global__ __launch_bounds__(256, 2) void point_kernel(
    const float* __restrict__ fm,   const int* __restrict__ bidx,
    const float* __restrict__ cond, const float* __restrict__ W1,
    const float* __restrict__ b1,   const float* __restrict__ W2,
    const float* __restrict__ b2,   int N, int numTiles)
{
    extern __shared__ char smem[];
    const uint32_t sbase = smem_u32(smem);
    const int t    = threadIdx.x;
    const int wid  = t >> 5;
    const int lane = t & 31;

    float* W1s   = (float*)(smem + OFF_W1);
    float* b1s   = (float*)(smem + OFF_B1);
    float* b2s   = (float*)(smem + OFF_B2);
    int*   bix   = (int*)(smem + OFF_BIDX);
    float* conds = (float*)(smem + OFF_COND);
    float* fms   = (float*)(smem + OFF_FM);
    float* pmax  = (float*)(smem + OFF_PMAX);
    float* Sa    = (float*)(smem + OFF_SA);
    float* Tb    = (float*)(smem + OFF_TB);

    // ---- one-time staging: W1/biases; W2 -> per-col two-digit int8 ----
    for (int i = t; i < 448; i += 256) W1s[i] = W1[i];
    if (t < 64)  b1s[t] = b1[t];
    if (t >= 128 && t < 256) b2s[t - 128] = b2[t - 128];
    if (t < 128) {
        const int n = t;
        float amax = 0.f;
        for (int k = 0; k < 64; k++) amax = fmaxf(amax, fabsf(W2[k * 128 + n]));
        const float invT = amax > 1e-37f ? 127.f / amax : 0.f;
        Tb[n] = amax * (1.f / 127.f);
        for (int q = 0; q < 4; q++) {           // 16 k-values per chunk
            unsigned u1[4], u2[4];
            #pragma unroll
            for (int v = 0; v < 4; v++) {
                int d1[4], d2[4];
                #pragma unroll
                for (int e = 0; e < 4; e++) {
                    float w  = W2[(q * 16 + v * 4 + e) * 128 + n];
                    float qq = w * invT;
                    float qr = rintf(qq);
                    d1[e] = (int)qr;
                    d2[e] = __float2int_rn((qq - qr) * 128.f);
                }
                u1[v] = pack4_s8(d1[0], d1[1], d1[2], d1[3]);
                u2[v] = pack4_s8(d2[0], d2[1], d2[2], d2[3]);
            }
            *(uint4*)(smem + OFF_B8 + n * 128 + ((q ^ (n & 7)) << 4)) =
                make_uint4(u1[0], u1[1], u1[2], u1[3]);
            *(uint4*)(smem + OFF_B8 + n * 128 + (((q + 4) ^ (n & 7)) << 4)) =
                make_uint4(u2[0], u2[1], u2[2], u2[3]);
        }
    }

    const int m    = t & 127;
    const int half = t >> 7;
    const int wm   = wid & 3;      // m 32-slice
    const int wn   = wid >> 2;     // n 64-slice

    for (int tile = blockIdx.x; tile < numTiles; tile += gridDim.x) {
        const int rbase = tile * 128;
        __syncthreads();           // prior epilogue reads (bix/A8/Sa) done

        // ---- phase A: stage inputs ----
        for (int i = t; i < 384; i += 256) {
            int g = rbase * 3 + i;
            fms[i] = (g < N * 3) ? fm[g] : 0.f;
        }
        if (t < 128) {
            int row = rbase + t;
            int b = (row < N) ? bidx[row] : -1;
            bix[t] = b;
            float4 c4 = make_float4(0.f, 0.f, 0.f, 0.f);
            if (b >= 0) c4 = *(const float4*)(cond + b * 4);
            *(float4*)(conds + t * 4) = c4;
        }
        __syncthreads();

        // ---- phase B1: layer 1 (row m, 32 cols) + local amax ----
        float h[32];
        {
            float in[7];
            in[0] = fms[m * 3 + 0]; in[1] = fms[m * 3 + 1]; in[2] = fms[m * 3 + 2];
            in[3] = conds[m * 4 + 0]; in[4] = conds[m * 4 + 1];
            in[5] = conds[m * 4 + 2]; in[6] = conds[m * 4 + 3];
            float am = 0.f;
            #pragma unroll
            for (int jj = 0; jj < 32; jj++) {
                const int j = (half << 5) + jj;
                float a = b1s[j];
                #pragma unroll
                for (int k = 0; k < 7; k++) a += in[k] * W1s[k * 64 + j];
                h[jj] = lrelu(a);
                am = fmaxf(am, fabsf(h[jj]));
            }
            pmax[t] = am;
        }
        __syncthreads();

        // ---- phase B2: row scale + two-digit quantize + swizzled store ----
        {
            const float am  = fmaxf(pmax[t], pmax[t ^ 128]);
            const float invS = am > 1e-37f ? 127.f / am : 0.f;
            if (half == 0) Sa[m] = am * (1.f / 127.f);
            #pragma unroll
            for (int q = 0; q < 2; q++) {        // two 16-col chunks
                unsigned u1[4], u2[4];
                #pragma unroll
                for (int v = 0; v < 4; v++) {
                    int d1[4], d2[4];
                    #pragma unroll
                    for (int e = 0; e < 4; e++) {
                        float qq = h[q * 16 + v * 4 + e] * invS;
                        float qr = rintf(qq);
                        d1[e] = (int)qr;
                        d2[e] = __float2int_rn((qq - qr) * 128.f);
                    }
                    u1[v] = pack4_s8(d1[0], d1[1], d1[2], d1[3]);
                    u2[v] = pack4_s8(d2[0], d2[1], d2[2], d2[3]);
                }
                const int c1 = ((half << 1) + q) ^ (m & 7);
                const int c2 = (4 + (half << 1) + q) ^ (m & 7);
                *(uint4*)(smem + OFF_A8 + m * 128 + (c1 << 4)) =
                    make_uint4(u1[0], u1[1], u1[2], u1[3]);
                *(uint4*)(smem + OFF_A8 + m * 128 + (c2 << 4)) =
                    make_uint4(u2[0], u2[1], u2[2], u2[3]);
            }
        }
        __syncthreads();

        // ---- phase C: A fragments (both digits) + row scales ----
        unsigned a1f[2][2][4], a2f[2][2][4];     // [kstep][mi][4]
        #pragma unroll
        for (int ks = 0; ks < 2; ks++)
            #pragma unroll
            for (int mi = 0; mi < 2; mi++) {
                const int arow = (wm << 5) + (mi << 4) + (lane & 15);
                const int chb  = (ks << 1) + (lane >> 4);
                ldsm4(a1f[ks][mi],
                      sbase + OFF_A8 + arow * 128 + ((chb ^ (arow & 7)) << 4));
                ldsm4(a2f[ks][mi],
                      sbase + OFF_A8 + arow * 128 + (((chb + 4) ^ (arow & 7)) << 4));
            }
        float sr[2][2];                           // [mi][rr]
        #pragma unroll
        for (int mi = 0; mi < 2; mi++)
            #pragma unroll
            for (int rr = 0; rr < 2; rr++)
                sr[mi][rr] = Sa[(wm << 5) + (mi << 4) + (rr << 3) + (lane >> 2)];

        // ---- phase D: 4 n-pairs: IMMA + combine + segmented max ----
        const int browb = (wn << 6) + (lane & 7) + ((lane >> 4) << 3);
        const int sbase_m = wm << 5;
        const int rA     = lane >> 2;
        const int blast  = bix[sbase_m + 31];
        #pragma unroll
        for (int p = 0; p < 4; p++) {
            unsigned b1r[2][4], b2r[2][4];
            #pragma unroll
            for (int ks = 0; ks < 2; ks++) {
                const int br  = browb + (p << 4);
                const int chb = (ks << 1) + ((lane >> 3) & 1);
                ldsm4(b1r[ks],
                      sbase + OFF_B8 + br * 128 + ((chb ^ (br & 7)) << 4));
                ldsm4(b2r[ks],
                      sbase + OFF_B8 + br * 128 + (((chb + 4) ^ (br & 7)) << 4));
            }
            int acc1[2][2][4], acc2[2][2][4];
            #pragma unroll
            for (int mi = 0; mi < 2; mi++)
                #pragma unroll
                for (int ni = 0; ni < 2; ni++)
                    #pragma unroll
                    for (int e = 0; e < 4; e++) { acc1[mi][ni][e] = 0; acc2[mi][ni][e] = 0; }
            #pragma unroll
            for (int ks = 0; ks < 2; ks++)
                #pragma unroll
                for (int mi = 0; mi < 2; mi++) {
                    imma(acc1[mi][0], a1f[ks][mi], b1r[ks][0], b1r[ks][1]);
                    imma(acc1[mi][1], a1f[ks][mi], b1r[ks][2], b1r[ks][3]);
                    imma(acc2[mi][0], a1f[ks][mi], b2r[ks][0], b2r[ks][1]);
                    imma(acc2[mi][1], a1f[ks][mi], b2r[ks][2], b2r[ks][3]);
                    imma(acc2[mi][0], a2f[ks][mi], b1r[ks][0], b1r[ks][1]);
                    imma(acc2[mi][1], a2f[ks][mi], b1r[ks][2], b1r[ks][3]);
                }
            // combine to float: d = S*T*(acc1 + acc2/128)
            float tc[2][2];
            #pragma unroll
            for (int ni = 0; ni < 2; ni++)
                #pragma unroll
                for (int e1 = 0; e1 < 2; e1++)
                    tc[ni][e1] = Tb[(wn << 6) + (p << 4) + (ni << 3) + ((lane & 3) << 1) + e1];
            float dp[2][2][4];
            #pragma unroll
            for (int mi = 0; mi < 2; mi++)
                #pragma unroll
                for (int ni = 0; ni < 2; ni++)
                    #pragma unroll
                    for (int e = 0; e < 4; e++) {
                        const float st = sr[mi][e >> 1] * tc[ni][e & 1] * 0.0078125f;
                        dp[mi][ni][e] =
                            (__int2float_rn(acc1[mi][ni][e]) * 128.f +
                             __int2float_rn(acc2[mi][ni][e])) * st;
                    }
            // segmented max over sorted rows + atomics
            int rstart = 0;
            while (rstart < 32) {
                const int cur = bix[sbase_m + rstart];
                int rend;
                if (blast == cur) rend = 32;
                else {
                    rend = rstart + 1;
                    while (rend < 32 && bix[sbase_m + rend] == cur) rend++;
                }
                const bool p0 = (rA      >= rstart) && (rA      < rend);
                const bool p1 = (rA + 8  >= rstart) && (rA + 8  < rend);
                const bool p2 = (rA + 16 >= rstart) && (rA + 16 < rend);
                const bool p3 = (rA + 24 >= rstart) && (rA + 24 < rend);
                float acc[4];
                #pragma unroll
                for (int ni = 0; ni < 2; ni++)
                    #pragma unroll
                    for (int e1 = 0; e1 < 2; e1++) {
                        float a = NEG_INIT;
                        if (p0) a = dp[0][ni][e1];
                        if (p1) a = fmaxf(a, dp[0][ni][2 + e1]);
                        if (p2) a = fmaxf(a, dp[1][ni][e1]);
                        if (p3) a = fmaxf(a, dp[1][ni][2 + e1]);
                        acc[ni * 2 + e1] = a;
                    }
                #pragma unroll
                for (int q = 0; q < 4; q++) {
                    acc[q] = fmaxf(acc[q], __shfl_xor_sync(0xFFFFFFFFu, acc[q], 4));
                    acc[q] = fmaxf(acc[q], __shfl_xor_sync(0xFFFFFFFFu, acc[q], 8));
                    acc[q] = fmaxf(acc[q], __shfl_xor_sync(0xFFFFFFFFu, acc[q], 16));
                }
                if (lane < 4 && cur >= 0) {
                    #pragma unroll
                    for (int ni = 0; ni < 2; ni++)
                        #pragma unroll
                        for (int e1 = 0; e1 < 2; e1++) {
                            const int c = (wn << 6) + (p << 4) + (ni << 3) + (lane << 1) + e1;
                            float y = lrelu(acc[ni * 2 + e1] + b2s[c]);
                            atomicMax(&g_gf[(cur << 7) + c], enc_f(y));
                        }
                }
                rstart = rend;
            }
        }
    }
}

// ---------------------------------------------------------------------------
// Decision MLP (unchanged)
// ---------------------------------------------------------------------------
__global__ __launch_bounds__(128) void decision_kernel(
    const float* __restrict__ cond, const float* __restrict__ W3,
    const float* __restrict__ b3,   const float* __restrict__ W4,
    const float* __restrict__ b4,   float* __restrict__ out, int B)
{
    extern __shared__ float sm[];
    float* W3s   = sm;
    float* b3s   = W3s + 16896;
    float* W4s   = b3s + 128;
    float* in_s  = W4s + 128;
    float* hid_s = in_s + 2112;

    const int t = threadIdx.x;
    {
        const float4* src = (const float4*)W3;
        float4* dst = (float4*)W3s;
        for (int i = t; i < 4224; i += 128) dst[i] = src[i];
    }
    b3s[t] = b3[t];
    W4s[t] = W4[t];

    const int b0 = blockIdx.x * 16;
    for (int i = t; i < 16 * 132; i += 128) {
        const int bi = i / 132, k = i % 132, bb = b0 + bi;
        float v = 0.f;
        if (bb < B)
            v = (k < 128) ? dec_f(g_gf[bb * 128 + k]) : cond[bb * 4 + (k - 128)];
        in_s[bi * 132 + k] = v;
    }
    __syncthreads();

    const int j = t;
    for (int i = 0; i < 16; i++) {
        float acc = b3s[j];
        #pragma unroll 4
        for (int k = 0; k < 132; k++) acc += in_s[i * 132 + k] * W3s[k * 128 + j];
        hid_s[i * 128 + j] = lrelu(acc);
    }
    __syncthreads();

    const int i = t >> 3, g = t & 7;
    float acc = 0.f;
    #pragma unroll
    for (int q = 0; q < 16; q++) acc += hid_s[i * 128 + g * 16 + q] * W4s[g * 16 + q];
    acc += __shfl_down_sync(0xFFFFFFFFu, acc, 4, 8);
    acc += __shfl_down_sync(0xFFFFFFFFu, acc, 2, 8);
    acc += __shfl_down_sync(0xFFFFFFFFu, acc, 1, 8);
    if (g == 0 && (b0 + i) < B) out[b0 + i] = acc + b4[0];
}

// ---------------------------------------------------------------------------
extern "C" void kernel_launch(void* const* d_in, const int* in_sizes, int n_in,
                              void* d_out, int out_size)
{
    const float* fm   = (const float*)d_in[0];
    const int*   bi   = (const int*)  d_in[1];
    const float* cond = (const float*)d_in[2];
    const int base = (n_in >= 12) ? 4 : 3;
    const float* W1 = (const float*)d_in[base + 0];
    const float* b1 = (const float*)d_in[base + 1];
    const float* W2 = (const float*)d_in[base + 2];
    const float* b2 = (const float*)d_in[base + 3];
    const float* W3 = (const float*)d_in[base + 4];
    const float* b3 = (const float*)d_in[base + 5];
    const float* W4 = (const float*)d_in[base + 6];
    const float* b4 = (const float*)d_in[base + 7];

    const int N = in_sizes[0] / 3;
    const int B = in_sizes[2] / 4;
    float* out = (float*)d_out;

    cudaFuncSetAttribute(point_kernel,
                         cudaFuncAttributeMaxDynamicSharedMemorySize, SMEM_BYTES);
    const int SMEM_B = 21312 * 4;
    cudaFuncSetAttribute(decision_kernel,
                         cudaFuncAttributeMaxDynamicSharedMemorySize, SMEM_B);

    const int total4 = B * 128 / 4;
    init_gf_kernel<<<(total4 + 255) / 256, 256>>>(total4);

    const int numTiles = (N + 127) / 128;
    point_kernel<<<296, 256, SMEM_BYTES>>>(fm, bi, cond, W1, b1, W2, b2, N, numTiles);

    decision_kernel<<<(B + 15) / 16, 128, SMEM_B>>>(cond, W3, b3, W4, b4, out, B);
}

// round 6
// speedup vs baseline: 1.2442x; 1.2442x over previous
#include <cuda_runtime.h>
#include <cuda_bf16.h>
#include <cstdint>

#define NEG_INIT -1.0e9f

// ---------------------------------------------------------------------------
__device__ __forceinline__ unsigned enc_f(float f) {
    unsigned u = __float_as_uint(f);
    return (u & 0x80000000u) ? ~u : (u | 0x80000000u);
}
__device__ __forceinline__ float dec_f(unsigned e) {
    unsigned u = (e & 0x80000000u) ? (e & 0x7FFFFFFFu) : ~e;
    return __uint_as_float(u);
}
__device__ __forceinline__ float lrelu(float x) { return x >= 0.f ? x : 0.2f * x; }

__device__ unsigned g_gf[16384 * 128];   // encoded global_feats scratch (8 MB)

__device__ __forceinline__ uint32_t smem_u32(const void* p) {
    uint32_t a;
    asm("{ .reg .u64 t; cvta.to.shared.u64 t, %1; cvt.u32.u64 %0, t; }" : "=r"(a) : "l"(p));
    return a;
}

#define SWZ(x) ((x) ^ (((x) >> 3) & 0x70))

__device__ __forceinline__ void ldsm4(unsigned r[4], uint32_t addr) {
    asm volatile("ldmatrix.sync.aligned.m8n8.x4.shared.b16 {%0,%1,%2,%3}, [%4];"
                 : "=r"(r[0]), "=r"(r[1]), "=r"(r[2]), "=r"(r[3]) : "r"(addr));
}
__device__ __forceinline__ void hmma(float d[4], const unsigned a[4],
                                     unsigned b0, unsigned b1) {
    asm volatile(
        "mma.sync.aligned.m16n8k16.row.col.f32.bf16.bf16.f32 "
        "{%0,%1,%2,%3}, {%4,%5,%6,%7}, {%8,%9}, {%0,%1,%2,%3};"
        : "+f"(d[0]), "+f"(d[1]), "+f"(d[2]), "+f"(d[3])
        : "r"(a[0]), "r"(a[1]), "r"(a[2]), "r"(a[3]), "r"(b0), "r"(b1));
}

__device__ __forceinline__ unsigned pack_bf16(float a, float b) {
    __nv_bfloat16 ha = __float2bfloat16(a), hb = __float2bfloat16(b);
    return ((unsigned)__bfloat16_as_ushort(hb) << 16) | __bfloat16_as_ushort(ha);
}
__device__ __forceinline__ unsigned cvt_bf16x2(float lo, float hi) {
    unsigned r;
    asm("cvt.rn.bf16x2.f32 %0, %1, %2;" : "=r"(r) : "f"(hi), "f"(lo));
    return r;
}

// ---------------------------------------------------------------------------
// SMEM layout (bytes)
// ---------------------------------------------------------------------------
#define OFF_BHI   0          // [128n][64k] bf16, SW128, 16384 B
#define OFF_BLO   16384
#define OFF_AHI   32768      // [128m][64k] bf16, SW128
#define OFF_ALO   49152
#define OFF_W1    65536      // 448 floats
#define OFF_B1    67328      // 64 floats
#define OFF_B2    67584      // 128 floats
#define OFF_BIDX  68096      // 128 ints
#define SMEM_BYTES 68608

// ---------------------------------------------------------------------------
__global__ void init_gf_kernel(int total4) {
    int i = blockIdx.x * blockDim.x + threadIdx.x;
    if (i < total4) {
        unsigned e = enc_f(NEG_INIT);
        ((uint4*)g_gf)[i] = make_uint4(e, e, e, e);
    }
}

// ---------------------------------------------------------------------------
// Persistent fused point kernel: layer1 (FFMA) + layer2 (HMMA bf16-split)
// + in-register segmented max.  Direct gmem loads with cross-tile prefetch.
// 256 threads, grid = 296.
// ---------------------------------------------------------------------------
__global__ __launch_bounds__(256, 2) void point_kernel(
    const float* __restrict__ fm,   const int* __restrict__ bidx,
    const float* __restrict__ cond, const float* __restrict__ W1,
    const float* __restrict__ b1,   const float* __restrict__ W2,
    const float* __restrict__ b2,   int N, int numTiles)
{
    extern __shared__ char smem[];
    const uint32_t sbase = smem_u32(smem);
    const int t    = threadIdx.x;
    const int wid  = t >> 5;
    const int lane = t & 31;

    float* W1s = (float*)(smem + OFF_W1);
    float* b1s = (float*)(smem + OFF_B1);
    float* b2s = (float*)(smem + OFF_B2);
    int*   bix = (int*)(smem + OFF_BIDX);

    // ---- one-time staging: W2 -> B hi/lo ([n][k] bf16, SW128), W1, biases ----
    for (int e = t; e < 4096; e += 256) {
        int n = e >> 5, k2 = e & 31;
        float w0 = W2[(2 * k2) * 128 + n];
        float w1 = W2[(2 * k2 + 1) * 128 + n];
        __nv_bfloat16 h0 = __float2bfloat16(w0), h1 = __float2bfloat16(w1);
        float r0 = w0 - __bfloat162float(h0), r1 = w1 - __bfloat162float(h1);
        unsigned hi = ((unsigned)__bfloat16_as_ushort(h1) << 16) | __bfloat16_as_ushort(h0);
        unsigned lo = pack_bf16(r0, r1);
        unsigned off = (unsigned)(n * 128 + k2 * 4);
        *(unsigned*)(smem + OFF_BHI + SWZ(off)) = hi;
        *(unsigned*)(smem + OFF_BLO + SWZ(off)) = lo;
    }
    for (int i = t; i < 448; i += 256) W1s[i] = W1[i];
    if (t < 64)  b1s[t] = b1[t];
    if (t < 128) b2s[t] = b2[t];
    __syncthreads();

    const int m    = t & 127;
    const int half = t >> 7;
    const int wm   = wid & 3;      // m 32-slice
    const int wn   = wid >> 2;     // n 64-slice

    // ---- initial prefetch for first tile ----
    int tile = blockIdx.x;
    float pin[7]; int pb;
    {
        const int row = tile * 128 + m;
        if (row < N) {
            pin[0] = fm[row * 3 + 0]; pin[1] = fm[row * 3 + 1]; pin[2] = fm[row * 3 + 2];
            pb = bidx[row];
            const float4 c4 = *(const float4*)(cond + pb * 4);
            pin[3] = c4.x; pin[4] = c4.y; pin[5] = c4.z; pin[6] = c4.w;
        } else {
            pb = -1;
            #pragma unroll
            for (int k = 0; k < 7; k++) pin[k] = 0.f;
        }
    }

    while (tile < numTiles) {
        // ---- phase B: layer 1 (row m, 32 cols) + split-store ----
        if (half == 0) bix[m] = pb;
        const int curb = pb;
        {
            float h[32];
            #pragma unroll
            for (int jj = 0; jj < 32; jj++) {
                const int j = (half << 5) + jj;
                float a = b1s[j];
                #pragma unroll
                for (int k = 0; k < 7; k++) a += pin[k] * W1s[k * 64 + j];
                h[jj] = lrelu(a);
            }
            // truncation split: hi = x & 0xFFFF0000, lo = x - hi
            #pragma unroll
            for (int q = 0; q < 4; q++) {
                uint4 uhi, ulo;
                unsigned u[8]; float lv[8];
                #pragma unroll
                for (int e = 0; e < 8; e++) {
                    float x = h[q * 8 + e];
                    u[e] = __float_as_uint(x);
                    lv[e] = x - __uint_as_float(u[e] & 0xFFFF0000u);
                }
                uhi.x = __byte_perm(u[0], u[1], 0x7632);
                uhi.y = __byte_perm(u[2], u[3], 0x7632);
                uhi.z = __byte_perm(u[4], u[5], 0x7632);
                uhi.w = __byte_perm(u[6], u[7], 0x7632);
                ulo.x = cvt_bf16x2(lv[0], lv[1]);
                ulo.y = cvt_bf16x2(lv[2], lv[3]);
                ulo.z = cvt_bf16x2(lv[4], lv[5]);
                ulo.w = cvt_bf16x2(lv[6], lv[7]);
                const int chunk = ((half << 2) + q) ^ (m & 7);
                *(uint4*)(smem + OFF_AHI + m * 128 + (chunk << 4)) = uhi;
                *(uint4*)(smem + OFF_ALO + m * 128 + (chunk << 4)) = ulo;
            }
        }
        __syncthreads();

        // ---- prefetch next tile's inputs (hidden behind MMA) ----
        const int next = tile + gridDim.x;
        {
            const int row = next * 128 + m;
            if (next < numTiles && row < N) {
                pin[0] = fm[row * 3 + 0]; pin[1] = fm[row * 3 + 1]; pin[2] = fm[row * 3 + 2];
                pb = bidx[row];
                const float4 c4 = *(const float4*)(cond + pb * 4);
                pin[3] = c4.x; pin[4] = c4.y; pin[5] = c4.z; pin[6] = c4.w;
            } else {
                pb = -1;
                #pragma unroll
                for (int k = 0; k < 7; k++) pin[k] = 0.f;
            }
        }

        // ---- phase C: layer 2 GEMM (HMMA, bf16 split x3) ----
        float d[2][8][4];
        #pragma unroll
        for (int mi = 0; mi < 2; mi++)
            #pragma unroll
            for (int ni = 0; ni < 8; ni++)
                #pragma unroll
                for (int e = 0; e < 4; e++) d[mi][ni][e] = 0.f;

        #pragma unroll
        for (int ks = 0; ks < 4; ks++) {
            int arow = (wm << 5) + (lane & 15);
            int akch = (ks << 1) + (lane >> 4);
            uint32_t aoff = (uint32_t)(arow * 128 + (((akch ^ (arow & 7)) & 7) << 4));
            unsigned ahi[2][4], alo[2][4];
            ldsm4(ahi[0], sbase + OFF_AHI + aoff);
            ldsm4(ahi[1], sbase + OFF_AHI + aoff + 16 * 128);
            ldsm4(alo[0], sbase + OFF_ALO + aoff);
            ldsm4(alo[1], sbase + OFF_ALO + aoff + 16 * 128);
            int brow = (wn << 6) + (lane & 7) + ((lane >> 4) << 3);
            int bkch = (ks << 1) + ((lane >> 3) & 1);
            uint32_t boff = (uint32_t)(brow * 128 + (((bkch ^ (brow & 7)) & 7) << 4));
            unsigned bf[4][4];
            #pragma unroll
            for (int g = 0; g < 4; g++) ldsm4(bf[g], sbase + OFF_BHI + boff + g * 2048);
            #pragma unroll
            for (int g = 0; g < 4; g++) {
                #pragma unroll
                for (int mi = 0; mi < 2; mi++) {
                    hmma(d[mi][2 * g + 0], ahi[mi], bf[g][0], bf[g][1]);
                    hmma(d[mi][2 * g + 1], ahi[mi], bf[g][2], bf[g][3]);
                    hmma(d[mi][2 * g + 0], alo[mi], bf[g][0], bf[g][1]);
                    hmma(d[mi][2 * g + 1], alo[mi], bf[g][2], bf[g][3]);
                }
            }
            #pragma unroll
            for (int g = 0; g < 4; g++) ldsm4(bf[g], sbase + OFF_BLO + boff + g * 2048);
            #pragma unroll
            for (int g = 0; g < 4; g++) {
                #pragma unroll
                for (int mi = 0; mi < 2; mi++) {
                    hmma(d[mi][2 * g + 0], ahi[mi], bf[g][0], bf[g][1]);
                    hmma(d[mi][2 * g + 1], ahi[mi], bf[g][2], bf[g][3]);
                }
            }
        }

        // ---- phase D: in-register segmented max + atomics (per warp) ----
        {
            const int base  = wm << 5;
            const int rA    = lane >> 2;
            const int bfirst = bix[base];
            const int blast  = bix[base + 31];
            if (bfirst == blast) {
                // fast path: single run covers all 32 rows (~87% of windows)
                float acc[16];
                #pragma unroll
                for (int ni = 0; ni < 8; ni++) {
                    float a0 = fmaxf(fmaxf(d[0][ni][0], d[0][ni][2]),
                                     fmaxf(d[1][ni][0], d[1][ni][2]));
                    float a1 = fmaxf(fmaxf(d[0][ni][1], d[0][ni][3]),
                                     fmaxf(d[1][ni][1], d[1][ni][3]));
                    acc[2 * ni] = a0; acc[2 * ni + 1] = a1;
                }
                #pragma unroll
                for (int q = 0; q < 16; q++) {
                    acc[q] = fmaxf(acc[q], __shfl_xor_sync(0xFFFFFFFFu, acc[q], 4));
                    acc[q] = fmaxf(acc[q], __shfl_xor_sync(0xFFFFFFFFu, acc[q], 8));
                    acc[q] = fmaxf(acc[q], __shfl_xor_sync(0xFFFFFFFFu, acc[q], 16));
                }
                if (lane < 4 && bfirst >= 0) {
                    #pragma unroll
                    for (int ni = 0; ni < 8; ni++) {
                        const int c = (wn << 6) + (ni << 3) + (lane << 1);
                        float y0 = lrelu(acc[2 * ni]     + b2s[c]);
                        float y1 = lrelu(acc[2 * ni + 1] + b2s[c + 1]);
                        atomicMax(&g_gf[(bfirst << 7) + c],     enc_f(y0));
                        atomicMax(&g_gf[(bfirst << 7) + c + 1], enc_f(y1));
                    }
                }
            } else {
                int rstart = 0;
                while (rstart < 32) {
                    const int cur = bix[base + rstart];
                    int rend;
                    if (blast == cur) rend = 32;
                    else {
                        rend = rstart + 1;
                        while (rend < 32 && bix[base + rend] == cur) rend++;
                    }
                    const bool p0 = (rA      >= rstart) && (rA      < rend);
                    const bool p1 = (rA + 8  >= rstart) && (rA + 8  < rend);
                    const bool p2 = (rA + 16 >= rstart) && (rA + 16 < rend);
                    const bool p3 = (rA + 24 >= rstart) && (rA + 24 < rend);
                    float acc[16];
                    #pragma unroll
                    for (int ni = 0; ni < 8; ni++) {
                        float a0 = NEG_INIT, a1 = NEG_INIT;
                        if (p0) { a0 = d[0][ni][0]; a1 = d[0][ni][1]; }
                        if (p1) { a0 = fmaxf(a0, d[0][ni][2]); a1 = fmaxf(a1, d[0][ni][3]); }
                        if (p2) { a0 = fmaxf(a0, d[1][ni][0]); a1 = fmaxf(a1, d[1][ni][1]); }
                        if (p3) { a0 = fmaxf(a0, d[1][ni][2]); a1 = fmaxf(a1, d[1][ni][3]); }
                        acc[2 * ni] = a0; acc[2 * ni + 1] = a1;
                    }
                    #pragma unroll
                    for (int q = 0; q < 16; q++) {
                        acc[q] = fmaxf(acc[q], __shfl_xor_sync(0xFFFFFFFFu, acc[q], 4));
                        acc[q] = fmaxf(acc[q], __shfl_xor_sync(0xFFFFFFFFu, acc[q], 8));
                        acc[q] = fmaxf(acc[q], __shfl_xor_sync(0xFFFFFFFFu, acc[q], 16));
                    }
                    if (lane < 4 && cur >= 0) {
                        #pragma unroll
                        for (int ni = 0; ni < 8; ni++) {
                            const int c = (wn << 6) + (ni << 3) + (lane << 1);
                            float y0 = lrelu(acc[2 * ni]     + b2s[c]);
                            float y1 = lrelu(acc[2 * ni + 1] + b2s[c + 1]);
                            atomicMax(&g_gf[(cur << 7) + c],     enc_f(y0));
                            atomicMax(&g_gf[(cur << 7) + c + 1], enc_f(y1));
                        }
                    }
                    rstart = rend;
                }
            }
        }
        __syncthreads();   // guard bix/A8 overwrite in next iteration
        tile = next;
    }
}

// ---------------------------------------------------------------------------
// Decision MLP (unchanged)
// ---------------------------------------------------------------------------
__global__ __launch_bounds__(128) void decision_kernel(
    const float* __restrict__ cond, const float* __restrict__ W3,
    const float* __restrict__ b3,   const float* __restrict__ W4,
    const float* __restrict__ b4,   float* __restrict__ out, int B)
{
    extern __shared__ float sm[];
    float* W3s   = sm;
    float* b3s   = W3s + 16896;
    float* W4s   = b3s + 128;
    float* in_s  = W4s + 128;
    float* hid_s = in_s + 2112;

    const int t = threadIdx.x;
    {
        const float4* src = (const float4*)W3;
        float4* dst = (float4*)W3s;
        for (int i = t; i < 4224; i += 128) dst[i] = src[i];
    }
    b3s[t] = b3[t];
    W4s[t] = W4[t];

    const int b0 = blockIdx.x * 16;
    for (int i = t; i < 16 * 132; i += 128) {
        const int bi = i / 132, k = i % 132, bb = b0 + bi;
        float v = 0.f;
        if (bb < B)
            v = (k < 128) ? dec_f(g_gf[bb * 128 + k]) : cond[bb * 4 + (k - 128)];
        in_s[bi * 132 + k] = v;
    }
    __syncthreads();

    const int j = t;
    for (int i = 0; i < 16; i++) {
        float acc = b3s[j];
        #pragma unroll 4
        for (int k = 0; k < 132; k++) acc += in_s[i * 132 + k] * W3s[k * 128 + j];
        hid_s[i * 128 + j] = lrelu(acc);
    }
    __syncthreads();

    const int i = t >> 3, g = t & 7;
    float acc = 0.f;
    #pragma unroll
    for (int q = 0; q < 16; q++) acc += hid_s[i * 128 + g * 16 + q] * W4s[g * 16 + q];
    acc += __shfl_down_sync(0xFFFFFFFFu, acc, 4, 8);
    acc += __shfl_down_sync(0xFFFFFFFFu, acc, 2, 8);
    acc += __shfl_down_sync(0xFFFFFFFFu, acc, 1, 8);
    if (g == 0 && (b0 + i) < B) out[b0 + i] = acc + b4[0];
}

// ---------------------------------------------------------------------------
extern "C" void kernel_launch(void* const* d_in, const int* in_sizes, int n_in,
                              void* d_out, int out_size)
{
    const float* fm   = (const float*)d_in[0];
    const int*   bi   = (const int*)  d_in[1];
    const float* cond = (const float*)d_in[2];
    const int base = (n_in >= 12) ? 4 : 3;
    const float* W1 = (const float*)d_in[base + 0];
    const float* b1 = (const float*)d_in[base + 1];
    const float* W2 = (const float*)d_in[base + 2];
    const float* b2 = (const float*)d_in[base + 3];
    const float* W3 = (const float*)d_in[base + 4];
    const float* b3 = (const float*)d_in[base + 5];
    const float* W4 = (const float*)d_in[base + 6];
    const float* b4 = (const float*)d_in[base + 7];

    const int N = in_sizes[0] / 3;
    const int B = in_sizes[2] / 4;
    float* out = (float*)d_out;

    cudaFuncSetAttribute(point_kernel,
                         cudaFuncAttributeMaxDynamicSharedMemorySize, SMEM_BYTES);
    const int SMEM_B = 21312 * 4;
    cudaFuncSetAttribute(decision_kernel,
                         cudaFuncAttributeMaxDynamicSharedMemorySize, SMEM_B);

    const int total4 = B * 128 / 4;
    init_gf_kernel<<<(total4 + 255) / 256, 256>>>(total4);

    const int numTiles = (N + 127) / 128;
    point_kernel<<<296, 256, SMEM_BYTES>>>(fm, bi, cond, W1, b1, W2, b2, N, numTiles);

    decision_kernel<<<(B + 15) / 16, 128, SMEM_B>>>(cond, W3, b3, W4, b4, out, B);
}

// round 7
// speedup vs baseline: 1.7344x; 1.3941x over previous
#include <cuda_runtime.h>
#include <cuda_fp16.h>
#include <cstdint>

#define NEG_INIT -1.0e9f

// ---------------------------------------------------------------------------
__device__ __forceinline__ unsigned enc_f(float f) {
    unsigned u = __float_as_uint(f);
    return (u & 0x80000000u) ? ~u : (u | 0x80000000u);
}
__device__ __forceinline__ float dec_f(unsigned e) {
    unsigned u = (e & 0x80000000u) ? (e & 0x7FFFFFFFu) : ~e;
    return __uint_as_float(u);
}
__device__ __forceinline__ float lrelu(float x) { return x >= 0.f ? x : 0.2f * x; }

__device__ unsigned g_gf[16384 * 128];   // encoded global_feats scratch (8 MB)

__device__ __forceinline__ uint32_t smem_u32(const void* p) {
    uint32_t a;
    asm("{ .reg .u64 t; cvta.to.shared.u64 t, %1; cvt.u32.u64 %0, t; }" : "=r"(a) : "l"(p));
    return a;
}

#define SWZ(x) ((x) ^ (((x) >> 3) & 0x70))

__device__ __forceinline__ void ldsm4(unsigned r[4], uint32_t addr) {
    asm volatile("ldmatrix.sync.aligned.m8n8.x4.shared.b16 {%0,%1,%2,%3}, [%4];"
                 : "=r"(r[0]), "=r"(r[1]), "=r"(r[2]), "=r"(r[3]) : "r"(addr));
}
__device__ __forceinline__ void hmma(float d[4], const unsigned a[4],
                                     unsigned b0, unsigned b1) {
    asm volatile(
        "mma.sync.aligned.m16n8k16.row.col.f32.f16.f16.f32 "
        "{%0,%1,%2,%3}, {%4,%5,%6,%7}, {%8,%9}, {%0,%1,%2,%3};"
        : "+f"(d[0]), "+f"(d[1]), "+f"(d[2]), "+f"(d[3])
        : "r"(a[0]), "r"(a[1]), "r"(a[2]), "r"(a[3]), "r"(b0), "r"(b1));
}
__device__ __forceinline__ unsigned cvt_f16x2(float lo, float hi) {
    unsigned r;
    asm("cvt.rn.f16x2.f32 %0, %1, %2;" : "=r"(r) : "f"(hi), "f"(lo));
    return r;
}

// ---------------------------------------------------------------------------
// SMEM layout (bytes)
// ---------------------------------------------------------------------------
#define OFF_B16   0          // [128n][64k] f16, SW128, 16384 B
#define OFF_A16   16384      // [128m][64k] f16, SW128
#define OFF_W1    32768      // 448 floats
#define OFF_B1    34560      // 64 floats
#define OFF_B2    34816      // 128 floats
#define OFF_BIDX  35328      // 128 ints
#define SMEM_BYTES 35840

// ---------------------------------------------------------------------------
__global__ void init_gf_kernel(int total4) {
    int i = blockIdx.x * blockDim.x + threadIdx.x;
    if (i < total4) {
        unsigned e = enc_f(NEG_INIT);
        ((uint4*)g_gf)[i] = make_uint4(e, e, e, e);
    }
}

// ---------------------------------------------------------------------------
// Persistent fused point kernel: layer1 (FFMA) + layer2 (single-product f16
// HMMA) + in-register segmented max.  256 threads, grid = 296.
// ---------------------------------------------------------------------------
__global__ __launch_bounds__(256, 2) void point_kernel(
    const float* __restrict__ fm,   const int* __restrict__ bidx,
    const float* __restrict__ cond, const float* __restrict__ W1,
    const float* __restrict__ b1,   const float* __restrict__ W2,
    const float* __restrict__ b2,   int N, int numTiles)
{
    extern __shared__ char smem[];
    const uint32_t sbase = smem_u32(smem);
    const int t    = threadIdx.x;
    const int wid  = t >> 5;
    const int lane = t & 31;

    float* W1s = (float*)(smem + OFF_W1);
    float* b1s = (float*)(smem + OFF_B1);
    float* b2s = (float*)(smem + OFF_B2);
    int*   bix = (int*)(smem + OFF_BIDX);

    // ---- one-time staging: W2 -> B f16 ([n][k], SW128), W1, biases ----
    for (int e = t; e < 4096; e += 256) {
        int n = e >> 5, k2 = e & 31;
        float w0 = W2[(2 * k2) * 128 + n];
        float w1 = W2[(2 * k2 + 1) * 128 + n];
        unsigned off = (unsigned)(n * 128 + k2 * 4);
        *(unsigned*)(smem + OFF_B16 + SWZ(off)) = cvt_f16x2(w0, w1);
    }
    for (int i = t; i < 448; i += 256) W1s[i] = W1[i];
    if (t < 64)  b1s[t] = b1[t];
    if (t < 128) b2s[t] = b2[t];
    __syncthreads();

    const int m    = t & 127;
    const int half = t >> 7;
    const int wm   = wid & 3;      // m 32-slice
    const int wn   = wid >> 2;     // n 64-slice

    // ---- initial prefetch for first tile ----
    int tile = blockIdx.x;
    float pin[7]; int pb;
    {
        const int row = tile * 128 + m;
        if (row < N) {
            pin[0] = fm[row * 3 + 0]; pin[1] = fm[row * 3 + 1]; pin[2] = fm[row * 3 + 2];
            pb = bidx[row];
            const float4 c4 = *(const float4*)(cond + pb * 4);
            pin[3] = c4.x; pin[4] = c4.y; pin[5] = c4.z; pin[6] = c4.w;
        } else {
            pb = -1;
            #pragma unroll
            for (int k = 0; k < 7; k++) pin[k] = 0.f;
        }
    }

    while (tile < numTiles) {
        // ---- phase B: layer 1 (row m, 32 cols) + f16 store ----
        if (half == 0) bix[m] = pb;
        {
            float h[32];
            #pragma unroll
            for (int jj = 0; jj < 32; jj++) {
                const int j = (half << 5) + jj;
                float a = b1s[j];
                #pragma unroll
                for (int k = 0; k < 7; k++) a += pin[k] * W1s[k * 64 + j];
                h[jj] = lrelu(a);
            }
            #pragma unroll
            for (int q = 0; q < 4; q++) {
                uint4 u;
                u.x = cvt_f16x2(h[q * 8 + 0], h[q * 8 + 1]);
                u.y = cvt_f16x2(h[q * 8 + 2], h[q * 8 + 3]);
                u.z = cvt_f16x2(h[q * 8 + 4], h[q * 8 + 5]);
                u.w = cvt_f16x2(h[q * 8 + 6], h[q * 8 + 7]);
                const int chunk = ((half << 2) + q) ^ (m & 7);
                *(uint4*)(smem + OFF_A16 + m * 128 + (chunk << 4)) = u;
            }
        }
        __syncthreads();

        // ---- prefetch next tile's inputs (hidden behind MMA) ----
        const int next = tile + gridDim.x;
        {
            const int row = next * 128 + m;
            if (next < numTiles && row < N) {
                pin[0] = fm[row * 3 + 0]; pin[1] = fm[row * 3 + 1]; pin[2] = fm[row * 3 + 2];
                pb = bidx[row];
                const float4 c4 = *(const float4*)(cond + pb * 4);
                pin[3] = c4.x; pin[4] = c4.y; pin[5] = c4.z; pin[6] = c4.w;
            } else {
                pb = -1;
                #pragma unroll
                for (int k = 0; k < 7; k++) pin[k] = 0.f;
            }
        }

        // ---- phase C: layer 2 GEMM (single-product f16 HMMA) ----
        float d[2][8][4];
        #pragma unroll
        for (int mi = 0; mi < 2; mi++)
            #pragma unroll
            for (int ni = 0; ni < 8; ni++)
                #pragma unroll
                for (int e = 0; e < 4; e++) d[mi][ni][e] = 0.f;

        #pragma unroll
        for (int ks = 0; ks < 4; ks++) {
            int arow = (wm << 5) + (lane & 15);
            int akch = (ks << 1) + (lane >> 4);
            uint32_t aoff = (uint32_t)(arow * 128 + (((akch ^ (arow & 7)) & 7) << 4));
            unsigned af[2][4];
            ldsm4(af[0], sbase + OFF_A16 + aoff);
            ldsm4(af[1], sbase + OFF_A16 + aoff + 16 * 128);
            int brow = (wn << 6) + (lane & 7) + ((lane >> 4) << 3);
            int bkch = (ks << 1) + ((lane >> 3) & 1);
            uint32_t boff = (uint32_t)(brow * 128 + (((bkch ^ (brow & 7)) & 7) << 4));
            unsigned bf[4][4];
            #pragma unroll
            for (int g = 0; g < 4; g++) ldsm4(bf[g], sbase + OFF_B16 + boff + g * 2048);
            #pragma unroll
            for (int g = 0; g < 4; g++) {
                #pragma unroll
                for (int mi = 0; mi < 2; mi++) {
                    hmma(d[mi][2 * g + 0], af[mi], bf[g][0], bf[g][1]);
                    hmma(d[mi][2 * g + 1], af[mi], bf[g][2], bf[g][3]);
                }
            }
        }

        // ---- phase D: in-register segmented max + atomics (per warp) ----
        {
            const int base  = wm << 5;
            const int rA    = lane >> 2;
            const int bfirst = bix[base];
            const int blast  = bix[base + 31];
            if (bfirst == blast) {
                // fast path: single run covers all 32 rows (~87% of windows)
                float acc[16];
                #pragma unroll
                for (int ni = 0; ni < 8; ni++) {
                    float a0 = fmaxf(fmaxf(d[0][ni][0], d[0][ni][2]),
                                     fmaxf(d[1][ni][0], d[1][ni][2]));
                    float a1 = fmaxf(fmaxf(d[0][ni][1], d[0][ni][3]),
                                     fmaxf(d[1][ni][1], d[1][ni][3]));
                    acc[2 * ni] = a0; acc[2 * ni + 1] = a1;
                }
                #pragma unroll
                for (int q = 0; q < 16; q++) {
                    acc[q] = fmaxf(acc[q], __shfl_xor_sync(0xFFFFFFFFu, acc[q], 4));
                    acc[q] = fmaxf(acc[q], __shfl_xor_sync(0xFFFFFFFFu, acc[q], 8));
                    acc[q] = fmaxf(acc[q], __shfl_xor_sync(0xFFFFFFFFu, acc[q], 16));
                }
                if (lane < 4 && bfirst >= 0) {
                    #pragma unroll
                    for (int ni = 0; ni < 8; ni++) {
                        const int c = (wn << 6) + (ni << 3) + (lane << 1);
                        float y0 = lrelu(acc[2 * ni]     + b2s[c]);
                        float y1 = lrelu(acc[2 * ni + 1] + b2s[c + 1]);
                        atomicMax(&g_gf[(bfirst << 7) + c],     enc_f(y0));
                        atomicMax(&g_gf[(bfirst << 7) + c + 1], enc_f(y1));
                    }
                }
            } else {
                int rstart = 0;
                while (rstart < 32) {
                    const int cur = bix[base + rstart];
                    int rend;
                    if (blast == cur) rend = 32;
                    else {
                        rend = rstart + 1;
                        while (rend < 32 && bix[base + rend] == cur) rend++;
                    }
                    const bool p0 = (rA      >= rstart) && (rA      < rend);
                    const bool p1 = (rA + 8  >= rstart) && (rA + 8  < rend);
                    const bool p2 = (rA + 16 >= rstart) && (rA + 16 < rend);
                    const bool p3 = (rA + 24 >= rstart) && (rA + 24 < rend);
                    float acc[16];
                    #pragma unroll
                    for (int ni = 0; ni < 8; ni++) {
                        float a0 = NEG_INIT, a1 = NEG_INIT;
                        if (p0) { a0 = d[0][ni][0]; a1 = d[0][ni][1]; }
                        if (p1) { a0 = fmaxf(a0, d[0][ni][2]); a1 = fmaxf(a1, d[0][ni][3]); }
                        if (p2) { a0 = fmaxf(a0, d[1][ni][0]); a1 = fmaxf(a1, d[1][ni][1]); }
                        if (p3) { a0 = fmaxf(a0, d[1][ni][2]); a1 = fmaxf(a1, d[1][ni][3]); }
                        acc[2 * ni] = a0; acc[2 * ni + 1] = a1;
                    }
                    #pragma unroll
                    for (int q = 0; q < 16; q++) {
                        acc[q] = fmaxf(acc[q], __shfl_xor_sync(0xFFFFFFFFu, acc[q], 4));
                        acc[q] = fmaxf(acc[q], __shfl_xor_sync(0xFFFFFFFFu, acc[q], 8));
                        acc[q] = fmaxf(acc[q], __shfl_xor_sync(0xFFFFFFFFu, acc[q], 16));
                    }
                    if (lane < 4 && cur >= 0) {
                        #pragma unroll
                        for (int ni = 0; ni < 8; ni++) {
                            const int c = (wn << 6) + (ni << 3) + (lane << 1);
                            float y0 = lrelu(acc[2 * ni]     + b2s[c]);
                            float y1 = lrelu(acc[2 * ni + 1] + b2s[c + 1]);
                            atomicMax(&g_gf[(cur << 7) + c],     enc_f(y0));
                            atomicMax(&g_gf[(cur << 7) + c + 1], enc_f(y1));
                        }
                    }
                    rstart = rend;
                }
            }
        }
        __syncthreads();   // guard bix/A16 overwrite in next iteration
        tile = next;
    }
}

// ---------------------------------------------------------------------------
// Decision MLP (unchanged)
// ---------------------------------------------------------------------------
__global__ __launch_bounds__(128) void decision_kernel(
    const float* __restrict__ cond, const float* __restrict__ W3,
    const float* __restrict__ b3,   const float* __restrict__ W4,
    const float* __restrict__ b4,   float* __restrict__ out, int B)
{
    extern __shared__ float sm[];
    float* W3s   = sm;
    float* b3s   = W3s + 16896;
    float* W4s   = b3s + 128;
    float* in_s  = W4s + 128;
    float* hid_s = in_s + 2112;

    const int t = threadIdx.x;
    {
        const float4* src = (const float4*)W3;
        float4* dst = (float4*)W3s;
        for (int i = t; i < 4224; i += 128) dst[i] = src[i];
    }
    b3s[t] = b3[t];
    W4s[t] = W4[t];

    const int b0 = blockIdx.x * 16;
    for (int i = t; i < 16 * 132; i += 128) {
        const int bi = i / 132, k = i % 132, bb = b0 + bi;
        float v = 0.f;
        if (bb < B)
            v = (k < 128) ? dec_f(g_gf[bb * 128 + k]) : cond[bb * 4 + (k - 128)];
        in_s[bi * 132 + k] = v;
    }
    __syncthreads();

    const int j = t;
    for (int i = 0; i < 16; i++) {
        float acc = b3s[j];
        #pragma unroll 4
        for (int k = 0; k < 132; k++) acc += in_s[i * 132 + k] * W3s[k * 128 + j];
        hid_s[i * 128 + j] = lrelu(acc);
    }
    __syncthreads();

    const int i = t >> 3, g = t & 7;
    float acc = 0.f;
    #pragma unroll
    for (int q = 0; q < 16; q++) acc += hid_s[i * 128 + g * 16 + q] * W4s[g * 16 + q];
    acc += __shfl_down_sync(0xFFFFFFFFu, acc, 4, 8);
    acc += __shfl_down_sync(0xFFFFFFFFu, acc, 2, 8);
    acc += __shfl_down_sync(0xFFFFFFFFu, acc, 1, 8);
    if (g == 0 && (b0 + i) < B) out[b0 + i] = acc + b4[0];
}

// ---------------------------------------------------------------------------
extern "C" void kernel_launch(void* const* d_in, const int* in_sizes, int n_in,
                              void* d_out, int out_size)
{
    const float* fm   = (const float*)d_in[0];
    const int*   bi   = (const int*)  d_in[1];
    const float* cond = (const float*)d_in[2];
    const int base = (n_in >= 12) ? 4 : 3;
    const float* W1 = (const float*)d_in[base + 0];
    const float* b1 = (const float*)d_in[base + 1];
    const float* W2 = (const float*)d_in[base + 2];
    const float* b2 = (const float*)d_in[base + 3];
    const float* W3 = (const float*)d_in[base + 4];
    const float* b3 = (const float*)d_in[base + 5];
    const float* W4 = (const float*)d_in[base + 6];
    const float* b4 = (const float*)d_in[base + 7];

    const int N = in_sizes[0] / 3;
    const int B = in_sizes[2] / 4;
    float* out = (float*)d_out;

    cudaFuncSetAttribute(point_kernel,
                         cudaFuncAttributeMaxDynamicSharedMemorySize, SMEM_BYTES);
    const int SMEM_B = 21312 * 4;
    cudaFuncSetAttribute(decision_kernel,
                         cudaFuncAttributeMaxDynamicSharedMemorySize, SMEM_B);

    const int total4 = B * 128 / 4;
    init_gf_kernel<<<(total4 + 255) / 256, 256>>>(total4);

    const int numTiles = (N + 127) / 128;
    point_kernel<<<296, 256, SMEM_BYTES>>>(fm, bi, cond, W1, b1, W2, b2, N, numTiles);

    decision_kernel<<<(B + 15) / 16, 128, SMEM_B>>>(cond, W3, b3, W4, b4, out, B);
}

// round 10
// speedup vs baseline: 1.8436x; 1.0630x over previous
#include <cuda_runtime.h>
#include <cuda_fp16.h>
#include <cstdint>

#define NEG_INIT -1.0e9f

// ---------------------------------------------------------------------------
__device__ __forceinline__ unsigned enc_f(float f) {
    unsigned u = __float_as_uint(f);
    return (u & 0x80000000u) ? ~u : (u | 0x80000000u);
}
__device__ __forceinline__ float dec_f(unsigned e) {
    unsigned u = (e & 0x80000000u) ? (e & 0x7FFFFFFFu) : ~e;
    return __uint_as_float(u);
}
__device__ __forceinline__ float lrelu(float x) { return x >= 0.f ? x : 0.2f * x; }

__device__ unsigned g_gf[16384 * 128];   // encoded global_feats scratch (8 MB)

__device__ __forceinline__ uint32_t smem_u32(const void* p) {
    uint32_t a;
    asm("{ .reg .u64 t; cvta.to.shared.u64 t, %1; cvt.u32.u64 %0, t; }" : "=r"(a) : "l"(p));
    return a;
}

#define SWZ(x) ((x) ^ (((x) >> 3) & 0x70))

__device__ __forceinline__ void ldsm4(unsigned r[4], uint32_t addr) {
    asm volatile("ldmatrix.sync.aligned.m8n8.x4.shared.b16 {%0,%1,%2,%3}, [%4];"
                 : "=r"(r[0]), "=r"(r[1]), "=r"(r[2]), "=r"(r[3]) : "r"(addr));
}
// f16 k16 MMA (layer 2)
__device__ __forceinline__ void hmma(float d[4], const unsigned a[4],
                                     unsigned b0, unsigned b1) {
    asm volatile(
        "mma.sync.aligned.m16n8k16.row.col.f32.f16.f16.f32 "
        "{%0,%1,%2,%3}, {%4,%5,%6,%7}, {%8,%9}, {%0,%1,%2,%3};"
        : "+f"(d[0]), "+f"(d[1]), "+f"(d[2]), "+f"(d[3])
        : "r"(a[0]), "r"(a[1]), "r"(a[2]), "r"(a[3]), "r"(b0), "r"(b1));
}
// bf16 k8 MMA (layer 1)
__device__ __forceinline__ void hmma_bf8(float d[4], unsigned a0, unsigned a1,
                                         unsigned b0) {
    asm volatile(
        "mma.sync.aligned.m16n8k8.row.col.f32.bf16.bf16.f32 "
        "{%0,%1,%2,%3}, {%4,%5}, {%6}, {%0,%1,%2,%3};"
        : "+f"(d[0]), "+f"(d[1]), "+f"(d[2]), "+f"(d[3])
        : "r"(a0), "r"(a1), "r"(b0));
}
__device__ __forceinline__ unsigned cvt_f16x2(float lo, float hi) {
    unsigned r;
    asm("cvt.rn.f16x2.f32 %0, %1, %2;" : "=r"(r) : "f"(hi), "f"(lo));
    return r;
}
__device__ __forceinline__ unsigned cvt_bf16x2(float lo, float hi) {
    unsigned r;
    asm("cvt.rn.bf16x2.f32 %0, %1, %2;" : "=r"(r) : "f"(hi), "f"(lo));
    return r;
}

// ---------------------------------------------------------------------------
// SMEM layout (bytes)
// ---------------------------------------------------------------------------
#define OFF_B16   0          // [128n][64k] f16, SW128 (W2), 16384 B
#define OFF_A16   16384      // [128m][64k] f16, SW128 (layer-1 out)
#define OFF_X     32768      // 2 x [128m][32B]: 16B bf16-hi k0-7 | 16B bf16-lo
#define OFF_W1A   40960      // [64n][32B]: bf16-hi k0-7 | bf16-lo (k7 = b1)
#define OFF_B2    43008      // 128 floats
#define OFF_BIDX  43520      // 2 x 128 ints
#define SMEM_BYTES 44544

// ---------------------------------------------------------------------------
__global__ void init_gf_kernel(int total4) {
    int i = blockIdx.x * blockDim.x + threadIdx.x;
    if (i < total4) {
        unsigned e = enc_f(NEG_INIT);
        ((uint4*)g_gf)[i] = make_uint4(e, e, e, e);
    }
}

// ---------------------------------------------------------------------------
// Persistent fused point kernel: layer1 (bf16-split MMA, bias via k7=1 trick)
// + layer2 (f16 MMA) + in-register segmented max.  256 threads, grid = 296.
// ---------------------------------------------------------------------------
__global__ __launch_bounds__(256, 2) void point_kernel(
    const float* __restrict__ fm,   const int* __restrict__ bidx,
    const float* __restrict__ cond, const float* __restrict__ W1,
    const float* __restrict__ b1,   const float* __restrict__ W2,
    const float* __restrict__ b2,   int N, int numTiles)
{
    extern __shared__ char smem[];
    const uint32_t sbase = smem_u32(smem);
    const int t    = threadIdx.x;
    const int wid  = t >> 5;
    const int lane = t & 31;

    float* b2s = (float*)(smem + OFF_B2);
    int*   bix = (int*)(smem + OFF_BIDX);

    // ---- one-time staging ----
    // W2 -> B16 f16 [n][k] SW128
    for (int e = t; e < 4096; e += 256) {
        int n = e >> 5, k2 = e & 31;
        float w0 = W2[(2 * k2) * 128 + n];
        float w1 = W2[(2 * k2 + 1) * 128 + n];
        unsigned off = (unsigned)(n * 128 + k2 * 4);
        *(unsigned*)(smem + OFF_B16 + SWZ(off)) = cvt_f16x2(w0, w1);
    }
    // W1 (+bias as k7) -> bf16 hi/lo rows of 32B
    if (t < 64) {
        float w[8];
        #pragma unroll
        for (int k = 0; k < 7; k++) w[k] = W1[k * 64 + t];
        w[7] = b1[t];
        unsigned u[8]; float l[8];
        #pragma unroll
        for (int e = 0; e < 8; e++) {
            u[e] = __float_as_uint(w[e]);
            l[e] = w[e] - __uint_as_float(u[e] & 0xFFFF0000u);
        }
        uint4 hi, lo;
        hi.x = __byte_perm(u[0], u[1], 0x7632);
        hi.y = __byte_perm(u[2], u[3], 0x7632);
        hi.z = __byte_perm(u[4], u[5], 0x7632);
        hi.w = __byte_perm(u[6], u[7], 0x7632);
        lo.x = cvt_bf16x2(l[0], l[1]); lo.y = cvt_bf16x2(l[2], l[3]);
        lo.z = cvt_bf16x2(l[4], l[5]); lo.w = cvt_bf16x2(l[6], l[7]);
        *(uint4*)(smem + OFF_W1A + t * 32)      = hi;
        *(uint4*)(smem + OFF_W1A + t * 32 + 16) = lo;
    }
    if (t < 128) b2s[t] = b2[t];

    const int m    = t & 127;
    const int half = t >> 7;
    const int wm   = wid & 3;      // m 32-slice
    const int wn   = wid >> 2;     // n 64-slice (layer2) / n 32-slice (layer1)

    // ---- prime: load + stage tile 0 inputs into X buf 0 ----
    int tile = blockIdx.x;
    int it   = 0;
    {
        const int row = tile * 128 + m;
        float pin[7]; int pb = -1;
        if (row < N) {
            pin[0] = fm[row * 3 + 0]; pin[1] = fm[row * 3 + 1]; pin[2] = fm[row * 3 + 2];
            pb = bidx[row];
            const float4 c4 = *(const float4*)(cond + pb * 4);
            pin[3] = c4.x; pin[4] = c4.y; pin[5] = c4.z; pin[6] = c4.w;
        } else {
            #pragma unroll
            for (int k = 0; k < 7; k++) pin[k] = 0.f;
        }
        if (half == 0) {
            unsigned u[7];
            #pragma unroll
            for (int e = 0; e < 7; e++) u[e] = __float_as_uint(pin[e]) & 0xFFFF0000u;
            uint4 hi;
            hi.x = __byte_perm(u[0], u[1], 0x7632);
            hi.y = __byte_perm(u[2], u[3], 0x7632);
            hi.z = __byte_perm(u[4], u[5], 0x7632);
            hi.w = __byte_perm(u[6], 0x3F800000u, 0x7632);   // k7 = 1.0 (exact)
            *(uint4*)(smem + OFF_X + m * 32) = hi;
            bix[m] = pb;
        } else {
            float l[7];
            #pragma unroll
            for (int e = 0; e < 7; e++)
                l[e] = pin[e] - __uint_as_float(__float_as_uint(pin[e]) & 0xFFFF0000u);
            uint4 lo;
            lo.x = cvt_bf16x2(l[0], l[1]); lo.y = cvt_bf16x2(l[2], l[3]);
            lo.z = cvt_bf16x2(l[4], l[5]); lo.w = cvt_bf16x2(l[6], 0.f);
            *(uint4*)(smem + OFF_X + m * 32 + 16) = lo;
        }
    }
    __syncthreads();

    while (tile < numTiles) {
        const int buf  = it & 1;
        const int nbuf = buf ^ 1;

        // ---- phase 1: layer 1 via bf16-split MMA -> A16 (f16) ----
        {
            unsigned xh[4], xl[4], wh[4], wl[4];
            const uint32_t xaddr = sbase + OFF_X + buf * 4096 + ((wm << 5) + lane) * 32;
            ldsm4(xh, xaddr);
            ldsm4(xl, xaddr + 16);
            const uint32_t waddr = sbase + OFF_W1A + ((wn << 5) + lane) * 32;
            ldsm4(wh, waddr);
            ldsm4(wl, waddr + 16);

            float d1[2][4][4];
            #pragma unroll
            for (int mt = 0; mt < 2; mt++)
                #pragma unroll
                for (int g = 0; g < 4; g++)
                    #pragma unroll
                    for (int e = 0; e < 4; e++) d1[mt][g][e] = 0.f;
            #pragma unroll
            for (int g = 0; g < 4; g++)
                #pragma unroll
                for (int mt = 0; mt < 2; mt++) {
                    hmma_bf8(d1[mt][g], xh[mt * 2], xh[mt * 2 + 1], wh[g]);
                    hmma_bf8(d1[mt][g], xl[mt * 2], xl[mt * 2 + 1], wh[g]);
                    hmma_bf8(d1[mt][g], xh[mt * 2], xh[mt * 2 + 1], wl[g]);
                }
            // epilogue: lrelu (fp32) -> f16x2 -> swizzled A16 store
            #pragma unroll
            for (int mt = 0; mt < 2; mt++) {
                const int r0 = (wm << 5) + (mt << 4) + (lane >> 2);
                #pragma unroll
                for (int g = 0; g < 4; g++) {
                    const int c = (wn << 5) + (g << 3) + ((lane & 3) << 1);
                    unsigned lo16 = cvt_f16x2(lrelu(d1[mt][g][0]), lrelu(d1[mt][g][1]));
                    unsigned hi16 = cvt_f16x2(lrelu(d1[mt][g][2]), lrelu(d1[mt][g][3]));
                    const int r1 = r0 + 8;
                    *(unsigned*)(smem + OFF_A16 + r0 * 128 +
                                 ((((c >> 3) ^ (r0 & 7)) & 7) << 4) + ((c & 7) << 1)) = lo16;
                    *(unsigned*)(smem + OFF_A16 + r1 * 128 +
                                 ((((c >> 3) ^ (r1 & 7)) & 7) << 4) + ((c & 7) << 1)) = hi16;
                }
            }
        }
        __syncthreads();

        // ---- phase 2a: load next tile's inputs (latency hidden by MMA) ----
        const int next = tile + gridDim.x;
        float pin[7]; int pb = -1; bool stage_next = (next < numTiles);
        if (stage_next) {
            const int row = next * 128 + m;
            if (row < N) {
                pin[0] = fm[row * 3 + 0]; pin[1] = fm[row * 3 + 1]; pin[2] = fm[row * 3 + 2];
                pb = bidx[row];
                const float4 c4 = *(const float4*)(cond + pb * 4);
                pin[3] = c4.x; pin[4] = c4.y; pin[5] = c4.z; pin[6] = c4.w;
            } else {
                #pragma unroll
                for (int k = 0; k < 7; k++) pin[k] = 0.f;
            }
        }

        // ---- phase 2b: layer 2 GEMM (single-product f16 HMMA) ----
        float d[2][8][4];
        #pragma unroll
        for (int mi = 0; mi < 2; mi++)
            #pragma unroll
            for (int ni = 0; ni < 8; ni++)
                #pragma unroll
                for (int e = 0; e < 4; e++) d[mi][ni][e] = 0.f;

        #pragma unroll
        for (int ks = 0; ks < 4; ks++) {
            int arow = (wm << 5) + (lane & 15);
            int akch = (ks << 1) + (lane >> 4);
            uint32_t aoff = (uint32_t)(arow * 128 + (((akch ^ (arow & 7)) & 7) << 4));
            unsigned af[2][4];
            ldsm4(af[0], sbase + OFF_A16 + aoff);
            ldsm4(af[1], sbase + OFF_A16 + aoff + 16 * 128);
            int brow = (wn << 6) + (lane & 7) + ((lane >> 4) << 3);
            int bkch = (ks << 1) + ((lane >> 3) & 1);
            uint32_t boff = (uint32_t)(brow * 128 + (((bkch ^ (brow & 7)) & 7) << 4));
            unsigned bf[4][4];
            #pragma unroll
            for (int g = 0; g < 4; g++) ldsm4(bf[g], sbase + OFF_B16 + boff + g * 2048);
            #pragma unroll
            for (int g = 0; g < 4; g++) {
                #pragma unroll
                for (int mi = 0; mi < 2; mi++) {
                    hmma(d[mi][2 * g + 0], af[mi], bf[g][0], bf[g][1]);
                    hmma(d[mi][2 * g + 1], af[mi], bf[g][2], bf[g][3]);
                }
            }
        }

        // ---- phase 2c: stage next tile's X (other buffer) ----
        if (stage_next) {
            if (half == 0) {
                unsigned u[7];
                #pragma unroll
                for (int e = 0; e < 7; e++) u[e] = __float_as_uint(pin[e]) & 0xFFFF0000u;
                uint4 hi;
                hi.x = __byte_perm(u[0], u[1], 0x7632);
                hi.y = __byte_perm(u[2], u[3], 0x7632);
                hi.z = __byte_perm(u[4], u[5], 0x7632);
                hi.w = __byte_perm(u[6], 0x3F800000u, 0x7632);
                *(uint4*)(smem + OFF_X + nbuf * 4096 + m * 32) = hi;
                bix[nbuf * 128 + m] = pb;
            } else {
                float l[7];
                #pragma unroll
                for (int e = 0; e < 7; e++)
                    l[e] = pin[e] - __uint_as_float(__float_as_uint(pin[e]) & 0xFFFF0000u);
                uint4 lo;
                lo.x = cvt_bf16x2(l[0], l[1]); lo.y = cvt_bf16x2(l[2], l[3]);
                lo.z = cvt_bf16x2(l[4], l[5]); lo.w = cvt_bf16x2(l[6], 0.f);
                *(uint4*)(smem + OFF_X + nbuf * 4096 + m * 32 + 16) = lo;
            }
        }

        // ---- phase 2d: in-register segmented max + atomics (per warp) ----
        {
            const int base  = buf * 128 + (wm << 5);
            const int rA    = lane >> 2;
            const int bfirst = bix[base];
            const int blast  = bix[base + 31];
            if (bfirst == blast) {
                float acc[16];
                #pragma unroll
                for (int ni = 0; ni < 8; ni++) {
                    float a0 = fmaxf(fmaxf(d[0][ni][0], d[0][ni][2]),
                                     fmaxf(d[1][ni][0], d[1][ni][2]));
                    float a1 = fmaxf(fmaxf(d[0][ni][1], d[0][ni][3]),
                                     fmaxf(d[1][ni][1], d[1][ni][3]));
                    acc[2 * ni] = a0; acc[2 * ni + 1] = a1;
                }
                #pragma unroll
                for (int q = 0; q < 16; q++) {
                    acc[q] = fmaxf(acc[q], __shfl_xor_sync(0xFFFFFFFFu, acc[q], 4));
                    acc[q] = fmaxf(acc[q], __shfl_xor_sync(0xFFFFFFFFu, acc[q], 8));
                    acc[q] = fmaxf(acc[q], __shfl_xor_sync(0xFFFFFFFFu, acc[q], 16));
                }
                if (lane < 4 && bfirst >= 0) {
                    #pragma unroll
                    for (int ni = 0; ni < 8; ni++) {
                        const int c = (wn << 6) + (ni << 3) + (lane << 1);
                        float y0 = lrelu(acc[2 * ni]     + b2s[c]);
                        float y1 = lrelu(acc[2 * ni + 1] + b2s[c + 1]);
                        atomicMax(&g_gf[(bfirst << 7) + c],     enc_f(y0));
                        atomicMax(&g_gf[(bfirst << 7) + c + 1], enc_f(y1));
                    }
                }
            } else {
                int rstart = 0;
                while (rstart < 32) {
                    const int cur = bix[base + rstart];
                    int rend;
                    if (blast == cur) rend = 32;
                    else {
                        rend = rstart + 1;
                        while (rend < 32 && bix[base + rend] == cur) rend++;
                    }
                    const bool p0 = (rA      >= rstart) && (rA      < rend);
                    const bool p1 = (rA + 8  >= rstart) && (rA + 8  < rend);
                    const bool p2 = (rA + 16 >= rstart) && (rA + 16 < rend);
                    const bool p3 = (rA + 24 >= rstart) && (rA + 24 < rend);
                    float acc[16];
                    #pragma unroll
                    for (int ni = 0; ni < 8; ni++) {
                        float a0 = NEG_INIT, a1 = NEG_INIT;
                        if (p0) { a0 = d[0][ni][0]; a1 = d[0][ni][1]; }
                        if (p1) { a0 = fmaxf(a0, d[0][ni][2]); a1 = fmaxf(a1, d[0][ni][3]); }
                        if (p2) { a0 = fmaxf(a0, d[1][ni][0]); a1 = fmaxf(a1, d[1][ni][1]); }
                        if (p3) { a0 = fmaxf(a0, d[1][ni][2]); a1 = fmaxf(a1, d[1][ni][3]); }
                        acc[2 * ni] = a0; acc[2 * ni + 1] = a1;
                    }
                    #pragma unroll
                    for (int q = 0; q < 16; q++) {
                        acc[q] = fmaxf(acc[q], __shfl_xor_sync(0xFFFFFFFFu, acc[q], 4));
                        acc[q] = fmaxf(acc[q], __shfl_xor_sync(0xFFFFFFFFu, acc[q], 8));
                        acc[q] = fmaxf(acc[q], __shfl_xor_sync(0xFFFFFFFFu, acc[q], 16));
                    }
                    if (lane < 4 && cur >= 0) {
                        #pragma unroll
                        for (int ni = 0; ni < 8; ni++) {
                            const int c = (wn << 6) + (ni << 3) + (lane << 1);
                            float y0 = lrelu(acc[2 * ni]     + b2s[c]);
                            float y1 = lrelu(acc[2 * ni + 1] + b2s[c + 1]);
                            atomicMax(&g_gf[(cur << 7) + c],     enc_f(y0));
                            atomicMax(&g_gf[(cur << 7) + c + 1], enc_f(y1));
                        }
                    }
                    rstart = rend;
                }
            }
        }
        __syncthreads();   // A16/X[buf]/bix reads done; X[nbuf]/bix[nbuf] visible
        tile = next; it++;
    }
}

// ---------------------------------------------------------------------------
// Decision MLP (unchanged)
// ---------------------------------------------------------------------------
__global__ __launch_bounds__(128) void decision_kernel(
    const float* __restrict__ cond, const float* __restrict__ W3,
    const float* __restrict__ b3,   const float* __restrict__ W4,
    const float* __restrict__ b4,   float* __restrict__ out, int B)
{
    extern __shared__ float sm[];
    float* W3s   = sm;
    float* b3s   = W3s + 16896;
    float* W4s   = b3s + 128;
    float* in_s  = W4s + 128;
    float* hid_s = in_s + 2112;

    const int t = threadIdx.x;
    {
        const float4* src = (const float4*)W3;
        float4* dst = (float4*)W3s;
        for (int i = t; i < 4224; i += 128) dst[i] = src[i];
    }
    b3s[t] = b3[t];
    W4s[t] = W4[t];

    const int b0 = blockIdx.x * 16;
    for (int i = t; i < 16 * 132; i += 128) {
        const int bi = i / 132, k = i % 132, bb = b0 + bi;
        float v = 0.f;
        if (bb < B)
            v = (k < 128) ? dec_f(g_gf[bb * 128 + k]) : cond[bb * 4 + (k - 128)];
        in_s[bi * 132 + k] = v;
    }
    __syncthreads();

    const int j = t;
    for (int i = 0; i < 16; i++) {
        float acc = b3s[j];
        #pragma unroll 4
        for (int k = 0; k < 132; k++) acc += in_s[i * 132 + k] * W3s[k * 128 + j];
        hid_s[i * 128 + j] = lrelu(acc);
    }
    __syncthreads();

    const int i = t >> 3, g = t & 7;
    float acc = 0.f;
    #pragma unroll
    for (int q = 0; q < 16; q++) acc += hid_s[i * 128 + g * 16 + q] * W4s[g * 16 + q];
    acc += __shfl_down_sync(0xFFFFFFFFu, acc, 4, 8);
    acc += __shfl_down_sync(0xFFFFFFFFu, acc, 2, 8);
    acc += __shfl_down_sync(0xFFFFFFFFu, acc, 1, 8);
    if (g == 0 && (b0 + i) < B) out[b0 + i] = acc + b4[0];
}

// ---------------------------------------------------------------------------
extern "C" void kernel_launch(void* const* d_in, const int* in_sizes, int n_in,
                              void* d_out, int out_size)
{
    const float* fm   = (const float*)d_in[0];
    const int*   bi   = (const int*)  d_in[1];
    const float* cond = (const float*)d_in[2];
    const int base = (n_in >= 12) ? 4 : 3;
    const float* W1 = (const float*)d_in[base + 0];
    const float* b1 = (const float*)d_in[base + 1];
    const float* W2 = (const float*)d_in[base + 2];
    const float* b2 = (const float*)d_in[base + 3];
    const float* W3 = (const float*)d_in[base + 4];
    const float* b3 = (const float*)d_in[base + 5];
    const float* W4 = (const float*)d_in[base + 6];
    const float* b4 = (const float*)d_in[base + 7];

    const int N = in_sizes[0] / 3;
    const int B = in_sizes[2] / 4;
    float* out = (float*)d_out;

    cudaFuncSetAttribute(point_kernel,
                         cudaFuncAttributeMaxDynamicSharedMemorySize, SMEM_BYTES);
    const int SMEM_B = 21312 * 4;
    cudaFuncSetAttribute(decision_kernel,
                         cudaFuncAttributeMaxDynamicSharedMemorySize, SMEM_B);

    const int total4 = B * 128 / 4;
    init_gf_kernel<<<(total4 + 255) / 256, 256>>>(total4);

    const int numTiles = (N + 127) / 128;
    point_kernel<<<296, 256, SMEM_BYTES>>>(fm, bi, cond, W1, b1, W2, b2, N, numTiles);

    decision_kernel<<<(B + 15) / 16, 128, SMEM_B>>>(cond, W3, b3, W4, b4, out, B);
}

// round 11
// speedup vs baseline: 2.1560x; 1.1694x over previous
#include <cuda_runtime.h>
#include <cuda_fp16.h>
#include <cstdint>

#define NEG_INIT -1.0e9f

// ---------------------------------------------------------------------------
__device__ __forceinline__ unsigned enc_f(float f) {
    unsigned u = __float_as_uint(f);
    return (u & 0x80000000u) ? ~u : (u | 0x80000000u);
}
__device__ __forceinline__ float dec_f(unsigned e) {
    unsigned u = (e & 0x80000000u) ? (e & 0x7FFFFFFFu) : ~e;
    return __uint_as_float(u);
}
__device__ __forceinline__ float lrelu(float x) { return x >= 0.f ? x : 0.2f * x; }

__device__ unsigned g_gf[16384 * 128];   // encoded global_feats scratch (8 MB)

__device__ __forceinline__ uint32_t smem_u32(const void* p) {
    uint32_t a;
    asm("{ .reg .u64 t; cvta.to.shared.u64 t, %1; cvt.u32.u64 %0, t; }" : "=r"(a) : "l"(p));
    return a;
}

#define SWZ(x) ((x) ^ (((x) >> 3) & 0x70))

// 2-warp (64-thread) named barrier for wm-group: ids 1..4
#define BAR_GROUP(id) asm volatile("bar.sync %0, 64;" :: "r"(id) : "memory")

__device__ __forceinline__ void ldsm4(unsigned r[4], uint32_t addr) {
    asm volatile("ldmatrix.sync.aligned.m8n8.x4.shared.b16 {%0,%1,%2,%3}, [%4];"
                 : "=r"(r[0]), "=r"(r[1]), "=r"(r[2]), "=r"(r[3]) : "r"(addr));
}
// f16 k16 MMA (layer 2)
__device__ __forceinline__ void hmma(float d[4], const unsigned a[4],
                                     unsigned b0, unsigned b1) {
    asm volatile(
        "mma.sync.aligned.m16n8k16.row.col.f32.f16.f16.f32 "
        "{%0,%1,%2,%3}, {%4,%5,%6,%7}, {%8,%9}, {%0,%1,%2,%3};"
        : "+f"(d[0]), "+f"(d[1]), "+f"(d[2]), "+f"(d[3])
        : "r"(a[0]), "r"(a[1]), "r"(a[2]), "r"(a[3]), "r"(b0), "r"(b1));
}
// bf16 k8 MMA (layer 1)
__device__ __forceinline__ void hmma_bf8(float d[4], unsigned a0, unsigned a1,
                                         unsigned b0) {
    asm volatile(
        "mma.sync.aligned.m16n8k8.row.col.f32.bf16.bf16.f32 "
        "{%0,%1,%2,%3}, {%4,%5}, {%6}, {%0,%1,%2,%3};"
        : "+f"(d[0]), "+f"(d[1]), "+f"(d[2]), "+f"(d[3])
        : "r"(a0), "r"(a1), "r"(b0));
}
__device__ __forceinline__ unsigned cvt_f16x2(float lo, float hi) {
    unsigned r;
    asm("cvt.rn.f16x2.f32 %0, %1, %2;" : "=r"(r) : "f"(hi), "f"(lo));
    return r;
}
__device__ __forceinline__ unsigned cvt_bf16x2(float lo, float hi) {
    unsigned r;
    asm("cvt.rn.bf16x2.f32 %0, %1, %2;" : "=r"(r) : "f"(hi), "f"(lo));
    return r;
}

// ---------------------------------------------------------------------------
// SMEM layout (bytes)
// ---------------------------------------------------------------------------
#define OFF_B16   0          // [128n][64k] f16, SW128 (W2), 16384 B
#define OFF_A16   16384      // [128m][64k] f16, SW128 (layer-1 out)
#define OFF_X     32768      // 2 x [128m][32B]: 16B bf16-hi k0-7 | 16B bf16-lo
#define OFF_W1A   40960      // [64n][32B]: bf16-hi k0-7 | bf16-lo (k7 = b1)
#define OFF_B2    43008      // 128 floats
#define OFF_BIDX  43520      // 2 x 128 ints
#define SMEM_BYTES 44544

// ---------------------------------------------------------------------------
__global__ void init_gf_kernel(int total4) {
    int i = blockIdx.x * blockDim.x + threadIdx.x;
    if (i < total4) {
        unsigned e = enc_f(NEG_INIT);
        ((uint4*)g_gf)[i] = make_uint4(e, e, e, e);
    }
}

// ---------------------------------------------------------------------------
// Persistent fused point kernel: layer1 (bf16-split MMA) + layer2 (f16 MMA)
// + in-register segmented max.  4 independent 2-warp pipelines per CTA via
// named barriers.  256 threads, grid = 296.
// ---------------------------------------------------------------------------
__global__ __launch_bounds__(256, 2) void point_kernel(
    const float* __restrict__ fm,   const int* __restrict__ bidx,
    const float* __restrict__ cond, const float* __restrict__ W1,
    const float* __restrict__ b1,   const float* __restrict__ W2,
    const float* __restrict__ b2,   int N, int numTiles)
{
    extern __shared__ char smem[];
    const uint32_t sbase = smem_u32(smem);
    const int t    = threadIdx.x;
    const int wid  = t >> 5;
    const int lane = t & 31;

    float* b2s = (float*)(smem + OFF_B2);
    int*   bix = (int*)(smem + OFF_BIDX);

    // ---- one-time staging ----
    // W2 -> B16 f16 [n][k] SW128
    for (int e = t; e < 4096; e += 256) {
        int n = e >> 5, k2 = e & 31;
        float w0 = W2[(2 * k2) * 128 + n];
        float w1 = W2[(2 * k2 + 1) * 128 + n];
        unsigned off = (unsigned)(n * 128 + k2 * 4);
        *(unsigned*)(smem + OFF_B16 + SWZ(off)) = cvt_f16x2(w0, w1);
    }
    // W1 (+bias as k7) -> bf16 hi/lo rows of 32B
    if (t < 64) {
        float w[8];
        #pragma unroll
        for (int k = 0; k < 7; k++) w[k] = W1[k * 64 + t];
        w[7] = b1[t];
        unsigned u[8]; float l[8];
        #pragma unroll
        for (int e = 0; e < 8; e++) {
            u[e] = __float_as_uint(w[e]);
            l[e] = w[e] - __uint_as_float(u[e] & 0xFFFF0000u);
        }
        uint4 hi, lo;
        hi.x = __byte_perm(u[0], u[1], 0x7632);
        hi.y = __byte_perm(u[2], u[3], 0x7632);
        hi.z = __byte_perm(u[4], u[5], 0x7632);
        hi.w = __byte_perm(u[6], u[7], 0x7632);
        lo.x = cvt_bf16x2(l[0], l[1]); lo.y = cvt_bf16x2(l[2], l[3]);
        lo.z = cvt_bf16x2(l[4], l[5]); lo.w = cvt_bf16x2(l[6], l[7]);
        *(uint4*)(smem + OFF_W1A + t * 32)      = hi;
        *(uint4*)(smem + OFF_W1A + t * 32 + 16) = lo;
    }
    if (t < 128) b2s[t] = b2[t];

    const int m    = t & 127;
    const int half = t >> 7;
    const int wm   = wid & 3;      // m 32-slice; group = warps {wm, wm+4}
    const int wn   = wid >> 2;     // n 64-slice (layer2) / n 32-slice (layer1)
    const int gbar = 1 + wm;       // named barrier id for this group

    // ---- prime: load + stage tile 0 inputs into X buf 0 ----
    int tile = blockIdx.x;
    int it   = 0;
    {
        const int row = tile * 128 + m;
        float pin[7]; int pb = -1;
        if (row < N) {
            pin[0] = fm[row * 3 + 0]; pin[1] = fm[row * 3 + 1]; pin[2] = fm[row * 3 + 2];
            pb = bidx[row];
            const float4 c4 = *(const float4*)(cond + pb * 4);
            pin[3] = c4.x; pin[4] = c4.y; pin[5] = c4.z; pin[6] = c4.w;
        } else {
            #pragma unroll
            for (int k = 0; k < 7; k++) pin[k] = 0.f;
        }
        if (half == 0) {
            unsigned u[7];
            #pragma unroll
            for (int e = 0; e < 7; e++) u[e] = __float_as_uint(pin[e]) & 0xFFFF0000u;
            uint4 hi;
            hi.x = __byte_perm(u[0], u[1], 0x7632);
            hi.y = __byte_perm(u[2], u[3], 0x7632);
            hi.z = __byte_perm(u[4], u[5], 0x7632);
            hi.w = __byte_perm(u[6], 0x3F800000u, 0x7632);   // k7 = 1.0 (exact)
            *(uint4*)(smem + OFF_X + m * 32) = hi;
            bix[m] = pb;
        } else {
            float l[7];
            #pragma unroll
            for (int e = 0; e < 7; e++)
                l[e] = pin[e] - __uint_as_float(__float_as_uint(pin[e]) & 0xFFFF0000u);
            uint4 lo;
            lo.x = cvt_bf16x2(l[0], l[1]); lo.y = cvt_bf16x2(l[2], l[3]);
            lo.z = cvt_bf16x2(l[4], l[5]); lo.w = cvt_bf16x2(l[6], 0.f);
            *(uint4*)(smem + OFF_X + m * 32 + 16) = lo;
        }
    }
    __syncthreads();   // full barrier: weights + tile-0 X visible to all

    while (tile < numTiles) {
        const int buf  = it & 1;
        const int nbuf = buf ^ 1;

        // ---- phase 1: layer 1 via bf16-split MMA -> A16 (f16) ----
        {
            unsigned xh[4], xl[4], wh[4], wl[4];
            const uint32_t xaddr = sbase + OFF_X + buf * 4096 + ((wm << 5) + lane) * 32;
            ldsm4(xh, xaddr);
            ldsm4(xl, xaddr + 16);
            const uint32_t waddr = sbase + OFF_W1A + ((wn << 5) + lane) * 32;
            ldsm4(wh, waddr);
            ldsm4(wl, waddr + 16);

            float d1[2][4][4];
            #pragma unroll
            for (int mt = 0; mt < 2; mt++)
                #pragma unroll
                for (int g = 0; g < 4; g++)
                    #pragma unroll
                    for (int e = 0; e < 4; e++) d1[mt][g][e] = 0.f;
            #pragma unroll
            for (int g = 0; g < 4; g++)
                #pragma unroll
                for (int mt = 0; mt < 2; mt++) {
                    hmma_bf8(d1[mt][g], xh[mt * 2], xh[mt * 2 + 1], wh[g]);
                    hmma_bf8(d1[mt][g], xl[mt * 2], xl[mt * 2 + 1], wh[g]);
                    hmma_bf8(d1[mt][g], xh[mt * 2], xh[mt * 2 + 1], wl[g]);
                }
            // epilogue: lrelu (fp32) -> f16x2 -> swizzled A16 store
            #pragma unroll
            for (int mt = 0; mt < 2; mt++) {
                const int r0 = (wm << 5) + (mt << 4) + (lane >> 2);
                #pragma unroll
                for (int g = 0; g < 4; g++) {
                    const int c = (wn << 5) + (g << 3) + ((lane & 3) << 1);
                    unsigned lo16 = cvt_f16x2(lrelu(d1[mt][g][0]), lrelu(d1[mt][g][1]));
                    unsigned hi16 = cvt_f16x2(lrelu(d1[mt][g][2]), lrelu(d1[mt][g][3]));
                    const int r1 = r0 + 8;
                    *(unsigned*)(smem + OFF_A16 + r0 * 128 +
                                 ((((c >> 3) ^ (r0 & 7)) & 7) << 4) + ((c & 7) << 1)) = lo16;
                    *(unsigned*)(smem + OFF_A16 + r1 * 128 +
                                 ((((c >> 3) ^ (r1 & 7)) & 7) << 4) + ((c & 7) << 1)) = hi16;
                }
            }
        }
        BAR_GROUP(gbar);   // A16 rows of this wm-group ready for both warps

        // ---- phase 2a: load next tile's inputs (latency hidden by MMA) ----
        const int next = tile + gridDim.x;
        float pin[7]; int pb = -1; bool stage_next = (next < numTiles);
        if (stage_next) {
            const int row = next * 128 + m;
            if (row < N) {
                pin[0] = fm[row * 3 + 0]; pin[1] = fm[row * 3 + 1]; pin[2] = fm[row * 3 + 2];
                pb = bidx[row];
                const float4 c4 = *(const float4*)(cond + pb * 4);
                pin[3] = c4.x; pin[4] = c4.y; pin[5] = c4.z; pin[6] = c4.w;
            } else {
                #pragma unroll
                for (int k = 0; k < 7; k++) pin[k] = 0.f;
            }
        }

        // ---- phase 2b: layer 2 GEMM (single-product f16 HMMA) ----
        float d[2][8][4];
        #pragma unroll
        for (int mi = 0; mi < 2; mi++)
            #pragma unroll
            for (int ni = 0; ni < 8; ni++)
                #pragma unroll
                for (int e = 0; e < 4; e++) d[mi][ni][e] = 0.f;

        #pragma unroll
        for (int ks = 0; ks < 4; ks++) {
            int arow = (wm << 5) + (lane & 15);
            int akch = (ks << 1) + (lane >> 4);
            uint32_t aoff = (uint32_t)(arow * 128 + (((akch ^ (arow & 7)) & 7) << 4));
            unsigned af[2][4];
            ldsm4(af[0], sbase + OFF_A16 + aoff);
            ldsm4(af[1], sbase + OFF_A16 + aoff + 16 * 128);
            int brow = (wn << 6) + (lane & 7) + ((lane >> 4) << 3);
            int bkch = (ks << 1) + ((lane >> 3) & 1);
            uint32_t boff = (uint32_t)(brow * 128 + (((bkch ^ (brow & 7)) & 7) << 4));
            unsigned bf[4][4];
            #pragma unroll
            for (int g = 0; g < 4; g++) ldsm4(bf[g], sbase + OFF_B16 + boff + g * 2048);
            #pragma unroll
            for (int g = 0; g < 4; g++) {
                #pragma unroll
                for (int mi = 0; mi < 2; mi++) {
                    hmma(d[mi][2 * g + 0], af[mi], bf[g][0], bf[g][1]);
                    hmma(d[mi][2 * g + 1], af[mi], bf[g][2], bf[g][3]);
                }
            }
        }

        // ---- phase 2c: stage next tile's X (other buffer) ----
        if (stage_next) {
            if (half == 0) {
                unsigned u[7];
                #pragma unroll
                for (int e = 0; e < 7; e++) u[e] = __float_as_uint(pin[e]) & 0xFFFF0000u;
                uint4 hi;
                hi.x = __byte_perm(u[0], u[1], 0x7632);
                hi.y = __byte_perm(u[2], u[3], 0x7632);
                hi.z = __byte_perm(u[4], u[5], 0x7632);
                hi.w = __byte_perm(u[6], 0x3F800000u, 0x7632);
                *(uint4*)(smem + OFF_X + nbuf * 4096 + m * 32) = hi;
                bix[nbuf * 128 + m] = pb;
            } else {
                float l[7];
                #pragma unroll
                for (int e = 0; e < 7; e++)
                    l[e] = pin[e] - __uint_as_float(__float_as_uint(pin[e]) & 0xFFFF0000u);
                uint4 lo;
                lo.x = cvt_bf16x2(l[0], l[1]); lo.y = cvt_bf16x2(l[2], l[3]);
                lo.z = cvt_bf16x2(l[4], l[5]); lo.w = cvt_bf16x2(l[6], 0.f);
                *(uint4*)(smem + OFF_X + nbuf * 4096 + m * 32 + 16) = lo;
            }
        }

        // ---- phase 2d: in-register segmented max + atomics (per warp) ----
        {
            const int base  = buf * 128 + (wm << 5);
            const int rA    = lane >> 2;
            const int bfirst = bix[base];
            const int blast  = bix[base + 31];
            if (bfirst == blast) {
                float acc[16];
                #pragma unroll
                for (int ni = 0; ni < 8; ni++) {
                    float a0 = fmaxf(fmaxf(d[0][ni][0], d[0][ni][2]),
                                     fmaxf(d[1][ni][0], d[1][ni][2]));
                    float a1 = fmaxf(fmaxf(d[0][ni][1], d[0][ni][3]),
                                     fmaxf(d[1][ni][1], d[1][ni][3]));
                    acc[2 * ni] = a0; acc[2 * ni + 1] = a1;
                }
                #pragma unroll
                for (int q = 0; q < 16; q++) {
                    acc[q] = fmaxf(acc[q], __shfl_xor_sync(0xFFFFFFFFu, acc[q], 4));
                    acc[q] = fmaxf(acc[q], __shfl_xor_sync(0xFFFFFFFFu, acc[q], 8));
                    acc[q] = fmaxf(acc[q], __shfl_xor_sync(0xFFFFFFFFu, acc[q], 16));
                }
                if (lane < 4 && bfirst >= 0) {
                    #pragma unroll
                    for (int ni = 0; ni < 8; ni++) {
                        const int c = (wn << 6) + (ni << 3) + (lane << 1);
                        float y0 = lrelu(acc[2 * ni]     + b2s[c]);
                        float y1 = lrelu(acc[2 * ni + 1] + b2s[c + 1]);
                        atomicMax(&g_gf[(bfirst << 7) + c],     enc_f(y0));
                        atomicMax(&g_gf[(bfirst << 7) + c + 1], enc_f(y1));
                    }
                }
            } else {
                int rstart = 0;
                while (rstart < 32) {
                    const int cur = bix[base + rstart];
                    int rend;
                    if (blast == cur) rend = 32;
                    else {
                        rend = rstart + 1;
                        while (rend < 32 && bix[base + rend] == cur) rend++;
                    }
                    const bool p0 = (rA      >= rstart) && (rA      < rend);
                    const bool p1 = (rA + 8  >= rstart) && (rA + 8  < rend);
                    const bool p2 = (rA + 16 >= rstart) && (rA + 16 < rend);
                    const bool p3 = (rA + 24 >= rstart) && (rA + 24 < rend);
                    float acc[16];
                    #pragma unroll
                    for (int ni = 0; ni < 8; ni++) {
                        float a0 = NEG_INIT, a1 = NEG_INIT;
                        if (p0) { a0 = d[0][ni][0]; a1 = d[0][ni][1]; }
                        if (p1) { a0 = fmaxf(a0, d[0][ni][2]); a1 = fmaxf(a1, d[0][ni][3]); }
                        if (p2) { a0 = fmaxf(a0, d[1][ni][0]); a1 = fmaxf(a1, d[1][ni][1]); }
                        if (p3) { a0 = fmaxf(a0, d[1][ni][2]); a1 = fmaxf(a1, d[1][ni][3]); }
                        acc[2 * ni] = a0; acc[2 * ni + 1] = a1;
                    }
                    #pragma unroll
                    for (int q = 0; q < 16; q++) {
                        acc[q] = fmaxf(acc[q], __shfl_xor_sync(0xFFFFFFFFu, acc[q], 4));
                        acc[q] = fmaxf(acc[q], __shfl_xor_sync(0xFFFFFFFFu, acc[q], 8));
                        acc[q] = fmaxf(acc[q], __shfl_xor_sync(0xFFFFFFFFu, acc[q], 16));
                    }
                    if (lane < 4 && cur >= 0) {
                        #pragma unroll
                        for (int ni = 0; ni < 8; ni++) {
                            const int c = (wn << 6) + (ni << 3) + (lane << 1);
                            float y0 = lrelu(acc[2 * ni]     + b2s[c]);
                            float y1 = lrelu(acc[2 * ni + 1] + b2s[c + 1]);
                            atomicMax(&g_gf[(cur << 7) + c],     enc_f(y0));
                            atomicMax(&g_gf[(cur << 7) + c + 1], enc_f(y1));
                        }
                    }
                    rstart = rend;
                }
            }
        }
        BAR_GROUP(gbar);   // group's A16/X[buf]/bix reads done; next X staged
        tile = next; it++;
    }
}

// ---------------------------------------------------------------------------
// Decision MLP (unchanged)
// ---------------------------------------------------------------------------
__global__ __launch_bounds__(128) void decision_kernel(
    const float* __restrict__ cond, const float* __restrict__ W3,
    const float* __restrict__ b3,   const float* __restrict__ W4,
    const float* __restrict__ b4,   float* __restrict__ out, int B)
{
    extern __shared__ float sm[];
    float* W3s   = sm;
    float* b3s   = W3s + 16896;
    float* W4s   = b3s + 128;
    float* in_s  = W4s + 128;
    float* hid_s = in_s + 2112;

    const int t = threadIdx.x;
    {
        const float4* src = (const float4*)W3;
        float4* dst = (float4*)W3s;
        for (int i = t; i < 4224; i += 128) dst[i] = src[i];
    }
    b3s[t] = b3[t];
    W4s[t] = W4[t];

    const int b0 = blockIdx.x * 16;
    for (int i = t; i < 16 * 132; i += 128) {
        const int bi = i / 132, k = i % 132, bb = b0 + bi;
        float v = 0.f;
        if (bb < B)
            v = (k < 128) ? dec_f(g_gf[bb * 128 + k]) : cond[bb * 4 + (k - 128)];
        in_s[bi * 132 + k] = v;
    }
    __syncthreads();

    const int j = t;
    for (int i = 0; i < 16; i++) {
        float acc = b3s[j];
        #pragma unroll 4
        for (int k = 0; k < 132; k++) acc += in_s[i * 132 + k] * W3s[k * 128 + j];
        hid_s[i * 128 + j] = lrelu(acc);
    }
    __syncthreads();

    const int i = t >> 3, g = t & 7;
    float acc = 0.f;
    #pragma unroll
    for (int q = 0; q < 16; q++) acc += hid_s[i * 128 + g * 16 + q] * W4s[g * 16 + q];
    acc += __shfl_down_sync(0xFFFFFFFFu, acc, 4, 8);
    acc += __shfl_down_sync(0xFFFFFFFFu, acc, 2, 8);
    acc += __shfl_down_sync(0xFFFFFFFFu, acc, 1, 8);
    if (g == 0 && (b0 + i) < B) out[b0 + i] = acc + b4[0];
}

// ---------------------------------------------------------------------------
extern "C" void kernel_launch(void* const* d_in, const int* in_sizes, int n_in,
                              void* d_out, int out_size)
{
    const float* fm   = (const float*)d_in[0];
    const int*   bi   = (const int*)  d_in[1];
    const float* cond = (const float*)d_in[2];
    const int base = (n_in >= 12) ? 4 : 3;
    const float* W1 = (const float*)d_in[base + 0];
    const float* b1 = (const float*)d_in[base + 1];
    const float* W2 = (const float*)d_in[base + 2];
    const float* b2 = (const float*)d_in[base + 3];
    const float* W3 = (const float*)d_in[base + 4];
    const float* b3 = (const float*)d_in[base + 5];
    const float* W4 = (const float*)d_in[base + 6];
    const float* b4 = (const float*)d_in[base + 7];

    const int N = in_sizes[0] / 3;
    const int B = in_sizes[2] / 4;
    float* out = (float*)d_out;

    cudaFuncSetAttribute(point_kernel,
                         cudaFuncAttributeMaxDynamicSharedMemorySize, SMEM_BYTES);
    const int SMEM_B = 21312 * 4;
    cudaFuncSetAttribute(decision_kernel,
                         cudaFuncAttributeMaxDynamicSharedMemorySize, SMEM_B);

    const int total4 = B * 128 / 4;
    init_gf_kernel<<<(total4 + 255) / 256, 256>>>(total4);

    const int numTiles = (N + 127) / 128;
    point_kernel<<<296, 256, SMEM_BYTES>>>(fm, bi, cond, W1, b1, W2, b2, N, numTiles);

    decision_kernel<<<(B + 15) / 16, 128, SMEM_B>>>(cond, W3, b3, W4, b4, out, B);
}

// round 12
// speedup vs baseline: 2.2385x; 1.0383x over previous
#include <cuda_runtime.h>
#include <cuda_fp16.h>
#include <cstdint>

#define NEG_INIT -1.0e9f

// ---------------------------------------------------------------------------
__device__ __forceinline__ unsigned enc_f(float f) {
    unsigned u = __float_as_uint(f);
    return (u & 0x80000000u) ? ~u : (u | 0x80000000u);
}
__device__ __forceinline__ float dec_f(unsigned e) {
    unsigned u = (e & 0x80000000u) ? (e & 0x7FFFFFFFu) : ~e;
    return __uint_as_float(u);
}
__device__ __forceinline__ float lrelu(float x) { return x >= 0.f ? x : 0.2f * x; }

__device__ unsigned g_gf[16384 * 128];   // encoded global_feats scratch (8 MB)

__device__ __forceinline__ uint32_t smem_u32(const void* p) {
    uint32_t a;
    asm("{ .reg .u64 t; cvta.to.shared.u64 t, %1; cvt.u32.u64 %0, t; }" : "=r"(a) : "l"(p));
    return a;
}

#define SWZ(x) ((x) ^ (((x) >> 3) & 0x70))

// 2-warp (64-thread) named barrier for wm-group: ids 1..4
#define BAR_GROUP(id) asm volatile("bar.sync %0, 64;" :: "r"(id) : "memory")

__device__ __forceinline__ void ldsm4(unsigned r[4], uint32_t addr) {
    asm volatile("ldmatrix.sync.aligned.m8n8.x4.shared.b16 {%0,%1,%2,%3}, [%4];"
                 : "=r"(r[0]), "=r"(r[1]), "=r"(r[2]), "=r"(r[3]) : "r"(addr));
}
// f16 k16 MMA (layer 2)
__device__ __forceinline__ void hmma(float d[4], const unsigned a[4],
                                     unsigned b0, unsigned b1) {
    asm volatile(
        "mma.sync.aligned.m16n8k16.row.col.f32.f16.f16.f32 "
        "{%0,%1,%2,%3}, {%4,%5,%6,%7}, {%8,%9}, {%0,%1,%2,%3};"
        : "+f"(d[0]), "+f"(d[1]), "+f"(d[2]), "+f"(d[3])
        : "r"(a[0]), "r"(a[1]), "r"(a[2]), "r"(a[3]), "r"(b0), "r"(b1));
}
// bf16 k8 MMA (layer 1)
__device__ __forceinline__ void hmma_bf8(float d[4], unsigned a0, unsigned a1,
                                         unsigned b0) {
    asm volatile(
        "mma.sync.aligned.m16n8k8.row.col.f32.bf16.bf16.f32 "
        "{%0,%1,%2,%3}, {%4,%5}, {%6}, {%0,%1,%2,%3};"
        : "+f"(d[0]), "+f"(d[1]), "+f"(d[2]), "+f"(d[3])
        : "r"(a0), "r"(a1), "r"(b0));
}
__device__ __forceinline__ unsigned cvt_f16x2(float lo, float hi) {
    unsigned r;
    asm("cvt.rn.f16x2.f32 %0, %1, %2;" : "=r"(r) : "f"(hi), "f"(lo));
    return r;
}
__device__ __forceinline__ unsigned cvt_bf16x2(float lo, float hi) {
    unsigned r;
    asm("cvt.rn.bf16x2.f32 %0, %1, %2;" : "=r"(r) : "f"(hi), "f"(lo));
    return r;
}

// ---------------------------------------------------------------------------
// SMEM layout (bytes)
// ---------------------------------------------------------------------------
#define OFF_B16   0          // [128n][64k] f16, SW128 (W2), 16384 B
#define OFF_A16   16384      // 2 x [128m][64k] f16, SW128 (layer-1 out), 32768 B
#define OFF_X     49152      // 4 x [128m][32B]: 16B bf16-hi k0-7 | 16B bf16-lo
#define OFF_W1A   65536      // [64n][32B]: bf16-hi k0-7 | bf16-lo (k7 = b1)
#define OFF_B2    67584      // 128 floats
#define OFF_BIDX  68096      // 4 x 128 ints
#define SMEM_BYTES 70144

// ---------------------------------------------------------------------------
__global__ void init_gf_kernel(int total4) {
    int i = blockIdx.x * blockDim.x + threadIdx.x;
    if (i < total4) {
        unsigned e = enc_f(NEG_INIT);
        ((uint4*)g_gf)[i] = make_uint4(e, e, e, e);
    }
}

// ---------------------------------------------------------------------------
// input load + X staging helpers
// ---------------------------------------------------------------------------
__device__ __forceinline__ void load_pin(
    const float* __restrict__ fm, const int* __restrict__ bidx,
    const float* __restrict__ cond, int tile, int numTiles, int m, int N,
    float pin[7], int& pb)
{
    pb = -1;
    #pragma unroll
    for (int k = 0; k < 7; k++) pin[k] = 0.f;
    if (tile < numTiles) {
        const int row = tile * 128 + m;
        if (row < N) {
            pin[0] = fm[row * 3 + 0]; pin[1] = fm[row * 3 + 1]; pin[2] = fm[row * 3 + 2];
            pb = bidx[row];
            const float4 c4 = *(const float4*)(cond + pb * 4);
            pin[3] = c4.x; pin[4] = c4.y; pin[5] = c4.z; pin[6] = c4.w;
        }
    }
}

__device__ __forceinline__ void stage_x(char* smem, int slot, int m, int half,
                                        const float pin[7], int pb)
{
    if (half == 0) {
        unsigned u[7];
        #pragma unroll
        for (int e = 0; e < 7; e++) u[e] = __float_as_uint(pin[e]) & 0xFFFF0000u;
        uint4 hi;
        hi.x = __byte_perm(u[0], u[1], 0x7632);
        hi.y = __byte_perm(u[2], u[3], 0x7632);
        hi.z = __byte_perm(u[4], u[5], 0x7632);
        hi.w = __byte_perm(u[6], 0x3F800000u, 0x7632);   // k7 = 1.0 (exact)
        *(uint4*)(smem + OFF_X + slot * 4096 + m * 32) = hi;
        ((int*)(smem + OFF_BIDX))[slot * 128 + m] = pb;
    } else {
        float l[7];
        #pragma unroll
        for (int e = 0; e < 7; e++)
            l[e] = pin[e] - __uint_as_float(__float_as_uint(pin[e]) & 0xFFFF0000u);
        uint4 lo;
        lo.x = cvt_bf16x2(l[0], l[1]); lo.y = cvt_bf16x2(l[2], l[3]);
        lo.z = cvt_bf16x2(l[4], l[5]); lo.w = cvt_bf16x2(l[6], 0.f);
        *(uint4*)(smem + OFF_X + slot * 4096 + m * 32 + 16) = lo;
    }
}

// ---------------------------------------------------------------------------
// Persistent fused point kernel: layer1 (bf16-split MMA) + layer2 (f16 MMA)
// + in-register segmented max.  4 independent 2-warp pipelines, ONE group
// barrier per tile (A16 x2, X/bix x4 ring staged 2 ahead).  grid = 296.
// ---------------------------------------------------------------------------
__global__ __launch_bounds__(256, 2) void point_kernel(
    const float* __restrict__ fm,   const int* __restrict__ bidx,
    const float* __restrict__ cond, const float* __restrict__ W1,
    const float* __restrict__ b1,   const float* __restrict__ W2,
    const float* __restrict__ b2,   int N, int numTiles)
{
    extern __shared__ char smem[];
    const uint32_t sbase = smem_u32(smem);
    const int t    = threadIdx.x;
    const int wid  = t >> 5;
    const int lane = t & 31;

    float* b2s = (float*)(smem + OFF_B2);
    int*   bix = (int*)(smem + OFF_BIDX);

    // ---- one-time staging ----
    for (int e = t; e < 4096; e += 256) {          // W2 -> B16 f16 [n][k] SW128
        int n = e >> 5, k2 = e & 31;
        float w0 = W2[(2 * k2) * 128 + n];
        float w1 = W2[(2 * k2 + 1) * 128 + n];
        unsigned off = (unsigned)(n * 128 + k2 * 4);
        *(unsigned*)(smem + OFF_B16 + SWZ(off)) = cvt_f16x2(w0, w1);
    }
    if (t < 64) {                                   // W1 (+bias as k7) bf16 hi/lo
        float w[8];
        #pragma unroll
        for (int k = 0; k < 7; k++) w[k] = W1[k * 64 + t];
        w[7] = b1[t];
        unsigned u[8]; float l[8];
        #pragma unroll
        for (int e = 0; e < 8; e++) {
            u[e] = __float_as_uint(w[e]);
            l[e] = w[e] - __uint_as_float(u[e] & 0xFFFF0000u);
        }
        uint4 hi, lo;
        hi.x = __byte_perm(u[0], u[1], 0x7632);
        hi.y = __byte_perm(u[2], u[3], 0x7632);
        hi.z = __byte_perm(u[4], u[5], 0x7632);
        hi.w = __byte_perm(u[6], u[7], 0x7632);
        lo.x = cvt_bf16x2(l[0], l[1]); lo.y = cvt_bf16x2(l[2], l[3]);
        lo.z = cvt_bf16x2(l[4], l[5]); lo.w = cvt_bf16x2(l[6], l[7]);
        *(uint4*)(smem + OFF_W1A + t * 32)      = hi;
        *(uint4*)(smem + OFF_W1A + t * 32 + 16) = lo;
    }
    if (t < 128) b2s[t] = b2[t];

    const int m    = t & 127;
    const int half = t >> 7;
    const int wm   = wid & 3;      // m 32-slice; group = warps {wm, wm+4}
    const int wn   = wid >> 2;     // n 64-slice (layer2) / n 32-slice (layer1)
    const int gbar = 1 + wm;       // named barrier id for this group
    const int G    = gridDim.x;

    // ---- prologue: stage tiles it=0 (slot0) and it=1 (slot1); hold it=2 ----
    int tile = blockIdx.x;
    float pin[7]; int pb;
    load_pin(fm, bidx, cond, tile, numTiles, m, N, pin, pb);
    stage_x(smem, 0, m, half, pin, pb);
    load_pin(fm, bidx, cond, tile + G, numTiles, m, N, pin, pb);
    stage_x(smem, 1, m, half, pin, pb);
    load_pin(fm, bidx, cond, tile + 2 * G, numTiles, m, N, pin, pb);
    __syncthreads();   // full barrier: weights + slots 0/1 visible to all

    // loop-invariant W1 fragments
    unsigned wh[4], wl[4];
    {
        const uint32_t waddr = sbase + OFF_W1A + ((wn << 5) + lane) * 32;
        ldsm4(wh, waddr);
        ldsm4(wl, waddr + 16);
    }

    int it = 0;
    while (tile < numTiles) {
        const int slot = it & 3;
        const uint32_t aoff_base = OFF_A16 + (unsigned)(it & 1) * 16384u;

        // ---- phase 1: layer 1 via bf16-split MMA -> A16[abuf] ----
        {
            unsigned xh[4], xl[4];
            const uint32_t xaddr = sbase + OFF_X + slot * 4096 + ((wm << 5) + lane) * 32;
            ldsm4(xh, xaddr);
            ldsm4(xl, xaddr + 16);

            float d1[2][4][4];
            #pragma unroll
            for (int mt = 0; mt < 2; mt++)
                #pragma unroll
                for (int g = 0; g < 4; g++)
                    #pragma unroll
                    for (int e = 0; e < 4; e++) d1[mt][g][e] = 0.f;
            #pragma unroll
            for (int g = 0; g < 4; g++)
                #pragma unroll
                for (int mt = 0; mt < 2; mt++) {
                    hmma_bf8(d1[mt][g], xh[mt * 2], xh[mt * 2 + 1], wh[g]);
                    hmma_bf8(d1[mt][g], xl[mt * 2], xl[mt * 2 + 1], wh[g]);
                    hmma_bf8(d1[mt][g], xh[mt * 2], xh[mt * 2 + 1], wl[g]);
                }
            // epilogue: lrelu -> f16x2 -> swizzled A16 store
            #pragma unroll
            for (int mt = 0; mt < 2; mt++) {
                const int r0 = (wm << 5) + (mt << 4) + (lane >> 2);
                #pragma unroll
                for (int g = 0; g < 4; g++) {
                    const int c = (wn << 5) + (g << 3) + ((lane & 3) << 1);
                    unsigned lo16 = cvt_f16x2(lrelu(d1[mt][g][0]), lrelu(d1[mt][g][1]));
                    unsigned hi16 = cvt_f16x2(lrelu(d1[mt][g][2]), lrelu(d1[mt][g][3]));
                    const int r1 = r0 + 8;
                    *(unsigned*)(smem + aoff_base + r0 * 128 +
                                 ((((c >> 3) ^ (r0 & 7)) & 7) << 4) + ((c & 7) << 1)) = lo16;
                    *(unsigned*)(smem + aoff_base + r1 * 128 +
                                 ((((c >> 3) ^ (r1 & 7)) & 7) << 4) + ((c & 7) << 1)) = hi16;
                }
            }
        }
        // stage tile it+2 into slot (it+2)&3 from regs loaded last phase 2
        stage_x(smem, (it + 2) & 3, m, half, pin, pb);
        BAR_GROUP(gbar);   // A16[abuf] + X/bix[(it+2)&3] visible to group

        // ---- phase 2a: issue loads for tile it+3 (held across barrier) ----
        load_pin(fm, bidx, cond, tile + 3 * G, numTiles, m, N, pin, pb);

        // ---- phase 2b: layer 2 GEMM (single-product f16 HMMA) ----
        float d[2][8][4];
        #pragma unroll
        for (int mi = 0; mi < 2; mi++)
            #pragma unroll
            for (int ni = 0; ni < 8; ni++)
                #pragma unroll
                for (int e = 0; e < 4; e++) d[mi][ni][e] = 0.f;

        #pragma unroll
        for (int ks = 0; ks < 4; ks++) {
            int arow = (wm << 5) + (lane & 15);
            int akch = (ks << 1) + (lane >> 4);
            uint32_t aoff = (uint32_t)(arow * 128 + (((akch ^ (arow & 7)) & 7) << 4));
            unsigned af[2][4];
            ldsm4(af[0], sbase + aoff_base + aoff);
            ldsm4(af[1], sbase + aoff_base + aoff + 16 * 128);
            int brow = (wn << 6) + (lane & 7) + ((lane >> 4) << 3);
            int bkch = (ks << 1) + ((lane >> 3) & 1);
            uint32_t boff = (uint32_t)(brow * 128 + (((bkch ^ (brow & 7)) & 7) << 4));
            unsigned bf[4][4];
            #pragma unroll
            for (int g = 0; g < 4; g++) ldsm4(bf[g], sbase + OFF_B16 + boff + g * 2048);
            #pragma unroll
            for (int g = 0; g < 4; g++) {
                #pragma unroll
                for (int mi = 0; mi < 2; mi++) {
                    hmma(d[mi][2 * g + 0], af[mi], bf[g][0], bf[g][1]);
                    hmma(d[mi][2 * g + 1], af[mi], bf[g][2], bf[g][3]);
                }
            }
        }

        // ---- phase 2c: in-register segmented max + atomics (per warp) ----
        {
            const int base  = slot * 128 + (wm << 5);
            const int rA    = lane >> 2;
            const int bfirst = bix[base];
            const int blast  = bix[base + 31];
            if (bfirst == blast) {
                float acc[16];
                #pragma unroll
                for (int ni = 0; ni < 8; ni++) {
                    float a0 = fmaxf(fmaxf(d[0][ni][0], d[0][ni][2]),
                                     fmaxf(d[1][ni][0], d[1][ni][2]));
                    float a1 = fmaxf(fmaxf(d[0][ni][1], d[0][ni][3]),
                                     fmaxf(d[1][ni][1], d[1][ni][3]));
                    acc[2 * ni] = a0; acc[2 * ni + 1] = a1;
                }
                #pragma unroll
                for (int q = 0; q < 16; q++) {
                    acc[q] = fmaxf(acc[q], __shfl_xor_sync(0xFFFFFFFFu, acc[q], 4));
                    acc[q] = fmaxf(acc[q], __shfl_xor_sync(0xFFFFFFFFu, acc[q], 8));
                    acc[q] = fmaxf(acc[q], __shfl_xor_sync(0xFFFFFFFFu, acc[q], 16));
                }
                if (lane < 4 && bfirst >= 0) {
                    #pragma unroll
                    for (int ni = 0; ni < 8; ni++) {
                        const int c = (wn << 6) + (ni << 3) + (lane << 1);
                        float y0 = lrelu(acc[2 * ni]     + b2s[c]);
                        float y1 = lrelu(acc[2 * ni + 1] + b2s[c + 1]);
                        atomicMax(&g_gf[(bfirst << 7) + c],     enc_f(y0));
                        atomicMax(&g_gf[(bfirst << 7) + c + 1], enc_f(y1));
                    }
                }
            } else {
                int rstart = 0;
                while (rstart < 32) {
                    const int cur = bix[base + rstart];
                    int rend;
                    if (blast == cur) rend = 32;
                    else {
                        rend = rstart + 1;
                        while (rend < 32 && bix[base + rend] == cur) rend++;
                    }
                    const bool p0 = (rA      >= rstart) && (rA      < rend);
                    const bool p1 = (rA + 8  >= rstart) && (rA + 8  < rend);
                    const bool p2 = (rA + 16 >= rstart) && (rA + 16 < rend);
                    const bool p3 = (rA + 24 >= rstart) && (rA + 24 < rend);
                    float acc[16];
                    #pragma unroll
                    for (int ni = 0; ni < 8; ni++) {
                        float a0 = NEG_INIT, a1 = NEG_INIT;
                        if (p0) { a0 = d[0][ni][0]; a1 = d[0][ni][1]; }
                        if (p1) { a0 = fmaxf(a0, d[0][ni][2]); a1 = fmaxf(a1, d[0][ni][3]); }
                        if (p2) { a0 = fmaxf(a0, d[1][ni][0]); a1 = fmaxf(a1, d[1][ni][1]); }
                        if (p3) { a0 = fmaxf(a0, d[1][ni][2]); a1 = fmaxf(a1, d[1][ni][3]); }
                        acc[2 * ni] = a0; acc[2 * ni + 1] = a1;
                    }
                    #pragma unroll
                    for (int q = 0; q < 16; q++) {
                        acc[q] = fmaxf(acc[q], __shfl_xor_sync(0xFFFFFFFFu, acc[q], 4));
                        acc[q] = fmaxf(acc[q], __shfl_xor_sync(0xFFFFFFFFu, acc[q], 8));
                        acc[q] = fmaxf(acc[q], __shfl_xor_sync(0xFFFFFFFFu, acc[q], 16));
                    }
                    if (lane < 4 && cur >= 0) {
                        #pragma unroll
                        for (int ni = 0; ni < 8; ni++) {
                            const int c = (wn << 6) + (ni << 3) + (lane << 1);
                            float y0 = lrelu(acc[2 * ni]     + b2s[c]);
                            float y1 = lrelu(acc[2 * ni + 1] + b2s[c + 1]);
                            atomicMax(&g_gf[(cur << 7) + c],     enc_f(y0));
                            atomicMax(&g_gf[(cur << 7) + c + 1], enc_f(y1));
                        }
                    }
                    rstart = rend;
                }
            }
        }
        tile += G; it++;
    }
}

// ---------------------------------------------------------------------------
// Decision MLP (unchanged)
// ---------------------------------------------------------------------------
__global__ __launch_bounds__(128) void decision_kernel(
    const float* __restrict__ cond, const float* __restrict__ W3,
    const float* __restrict__ b3,   const float* __restrict__ W4,
    const float* __restrict__ b4,   float* __restrict__ out, int B)
{
    extern __shared__ float sm[];
    float* W3s   = sm;
    float* b3s   = W3s + 16896;
    float* W4s   = b3s + 128;
    float* in_s  = W4s + 128;
    float* hid_s = in_s + 2112;

    const int t = threadIdx.x;
    {
        const float4* src = (const float4*)W3;
        float4* dst = (float4*)W3s;
        for (int i = t; i < 4224; i += 128) dst[i] = src[i];
    }
    b3s[t] = b3[t];
    W4s[t] = W4[t];

    const int b0 = blockIdx.x * 16;
    for (int i = t; i < 16 * 132; i += 128) {
        const int bi = i / 132, k = i % 132, bb = b0 + bi;
        float v = 0.f;
        if (bb < B)
            v = (k < 128) ? dec_f(g_gf[bb * 128 + k]) : cond[bb * 4 + (k - 128)];
        in_s[bi * 132 + k] = v;
    }
    __syncthreads();

    const int j = t;
    for (int i = 0; i < 16; i++) {
        float acc = b3s[j];
        #pragma unroll 4
        for (int k = 0; k < 132; k++) acc += in_s[i * 132 + k] * W3s[k * 128 + j];
        hid_s[i * 128 + j] = lrelu(acc);
    }
    __syncthreads();

    const int i = t >> 3, g = t & 7;
    float acc = 0.f;
    #pragma unroll
    for (int q = 0; q < 16; q++) acc += hid_s[i * 128 + g * 16 + q] * W4s[g * 16 + q];
    acc += __shfl_down_sync(0xFFFFFFFFu, acc, 4, 8);
    acc += __shfl_down_sync(0xFFFFFFFFu, acc, 2, 8);
    acc += __shfl_down_sync(0xFFFFFFFFu, acc, 1, 8);
    if (g == 0 && (b0 + i) < B) out[b0 + i] = acc + b4[0];
}

// ---------------------------------------------------------------------------
extern "C" void kernel_launch(void* const* d_in, const int* in_sizes, int n_in,
                              void* d_out, int out_size)
{
    const float* fm   = (const float*)d_in[0];
    const int*   bi   = (const int*)  d_in[1];
    const float* cond = (const float*)d_in[2];
    const int base = (n_in >= 12) ? 4 : 3;
    const float* W1 = (const float*)d_in[base + 0];
    const float* b1 = (const float*)d_in[base + 1];
    const float* W2 = (const float*)d_in[base + 2];
    const float* b2 = (const float*)d_in[base + 3];
    const float* W3 = (const float*)d_in[base + 4];
    const float* b3 = (const float*)d_in[base + 5];
    const float* W4 = (const float*)d_in[base + 6];
    const float* b4 = (const float*)d_in[base + 7];

    const int N = in_sizes[0] / 3;
    const int B = in_sizes[2] / 4;
    float* out = (float*)d_out;

    cudaFuncSetAttribute(point_kernel,
                         cudaFuncAttributeMaxDynamicSharedMemorySize, SMEM_BYTES);
    const int SMEM_B = 21312 * 4;
    cudaFuncSetAttribute(decision_kernel,
                         cudaFuncAttributeMaxDynamicSharedMemorySize, SMEM_B);

    const int total4 = B * 128 / 4;
    init_gf_kernel<<<(total4 + 255) / 256, 256>>>(total4);

    const int numTiles = (N + 127) / 128;
    point_kernel<<<296, 256, SMEM_BYTES>>>(fm, bi, cond, W1, b1, W2, b2, N, numTiles);

    decision_kernel<<<(B + 15) / 16, 128, SMEM_B>>>(cond, W3, b3, W4, b4, out, B);
}

// round 13
// speedup vs baseline: 2.2475x; 1.0040x over previous
#include <cuda_runtime.h>
#include <cuda_fp16.h>
#include <cstdint>

#define NEG_INIT -1.0e9f

// ---------------------------------------------------------------------------
__device__ __forceinline__ unsigned enc_f(float f) {
    unsigned u = __float_as_uint(f);
    return (u & 0x80000000u) ? ~u : (u | 0x80000000u);
}
__device__ __forceinline__ float dec_f(unsigned e) {
    unsigned u = (e & 0x80000000u) ? (e & 0x7FFFFFFFu) : ~e;
    return __uint_as_float(u);
}
__device__ __forceinline__ float lrelu(float x) { return x >= 0.f ? x : 0.2f * x; }

__device__ unsigned g_gf[16384 * 128];   // encoded global_feats scratch (8 MB)

__device__ __forceinline__ uint32_t smem_u32(const void* p) {
    uint32_t a;
    asm("{ .reg .u64 t; cvta.to.shared.u64 t, %1; cvt.u32.u64 %0, t; }" : "=r"(a) : "l"(p));
    return a;
}

#define SWZ(x) ((x) ^ (((x) >> 3) & 0x70))

// 2-warp (64-thread) named barrier for wm-group: ids 1..4
#define BAR_GROUP(id) asm volatile("bar.sync %0, 64;" :: "r"(id) : "memory")

__device__ __forceinline__ void ldsm4(unsigned r[4], uint32_t addr) {
    asm volatile("ldmatrix.sync.aligned.m8n8.x4.shared.b16 {%0,%1,%2,%3}, [%4];"
                 : "=r"(r[0]), "=r"(r[1]), "=r"(r[2]), "=r"(r[3]) : "r"(addr));
}
// f16 k16 MMA (layer 2)
__device__ __forceinline__ void hmma(float d[4], const unsigned a[4],
                                     unsigned b0, unsigned b1) {
    asm volatile(
        "mma.sync.aligned.m16n8k16.row.col.f32.f16.f16.f32 "
        "{%0,%1,%2,%3}, {%4,%5,%6,%7}, {%8,%9}, {%0,%1,%2,%3};"
        : "+f"(d[0]), "+f"(d[1]), "+f"(d[2]), "+f"(d[3])
        : "r"(a[0]), "r"(a[1]), "r"(a[2]), "r"(a[3]), "r"(b0), "r"(b1));
}
// bf16 k8 MMA (layer 1)
__device__ __forceinline__ void hmma_bf8(float d[4], unsigned a0, unsigned a1,
                                         unsigned b0) {
    asm volatile(
        "mma.sync.aligned.m16n8k8.row.col.f32.bf16.bf16.f32 "
        "{%0,%1,%2,%3}, {%4,%5}, {%6}, {%0,%1,%2,%3};"
        : "+f"(d[0]), "+f"(d[1]), "+f"(d[2]), "+f"(d[3])
        : "r"(a0), "r"(a1), "r"(b0));
}
__device__ __forceinline__ unsigned cvt_f16x2(float lo, float hi) {
    unsigned r;
    asm("cvt.rn.f16x2.f32 %0, %1, %2;" : "=r"(r) : "f"(hi), "f"(lo));
    return r;
}
__device__ __forceinline__ unsigned cvt_bf16x2(float lo, float hi) {
    unsigned r;
    asm("cvt.rn.bf16x2.f32 %0, %1, %2;" : "=r"(r) : "f"(hi), "f"(lo));
    return r;
}

// ---------------------------------------------------------------------------
// SMEM layout (bytes)
// ---------------------------------------------------------------------------
#define OFF_B16   0          // [128n][64k] f16, SW128 (W2), 16384 B
#define OFF_A16   16384      // 2 x [128m][64k] f16, SW128 (layer-1 out), 32768 B
#define OFF_X     49152      // 4 x [128m][32B]: 16B bf16-hi k0-7 | 16B bf16-lo
#define OFF_W1A   65536      // [64n][32B]: bf16-hi k0-7 | bf16-lo (k7 = b1)
#define OFF_B2    67584      // 128 floats
#define OFF_BIDX  68096      // 4 x 128 ints
#define SMEM_BYTES 70144

// ---------------------------------------------------------------------------
__global__ void init_gf_kernel(int total4) {
    int i = blockIdx.x * blockDim.x + threadIdx.x;
    if (i < total4) {
        unsigned e = enc_f(NEG_INIT);
        ((uint4*)g_gf)[i] = make_uint4(e, e, e, e);
    }
}

// ---------------------------------------------------------------------------
// input load + X staging helpers
// ---------------------------------------------------------------------------
__device__ __forceinline__ void load_pin(
    const float* __restrict__ fm, const int* __restrict__ bidx,
    const float* __restrict__ cond, int tile, int numTiles, int m, int N,
    float pin[7], int& pb)
{
    pb = -1;
    #pragma unroll
    for (int k = 0; k < 7; k++) pin[k] = 0.f;
    if (tile < numTiles) {
        const int row = tile * 128 + m;
        if (row < N) {
            pin[0] = fm[row * 3 + 0]; pin[1] = fm[row * 3 + 1]; pin[2] = fm[row * 3 + 2];
            pb = bidx[row];
            const float4 c4 = *(const float4*)(cond + pb * 4);
            pin[3] = c4.x; pin[4] = c4.y; pin[5] = c4.z; pin[6] = c4.w;
        }
    }
}

__device__ __forceinline__ void stage_x(char* smem, int slot, int m, int half,
                                        const float pin[7], int pb)
{
    if (half == 0) {
        unsigned u[7];
        #pragma unroll
        for (int e = 0; e < 7; e++) u[e] = __float_as_uint(pin[e]) & 0xFFFF0000u;
        uint4 hi;
        hi.x = __byte_perm(u[0], u[1], 0x7632);
        hi.y = __byte_perm(u[2], u[3], 0x7632);
        hi.z = __byte_perm(u[4], u[5], 0x7632);
        hi.w = __byte_perm(u[6], 0x3F800000u, 0x7632);   // k7 = 1.0 (exact)
        *(uint4*)(smem + OFF_X + slot * 4096 + m * 32) = hi;
        ((int*)(smem + OFF_BIDX))[slot * 128 + m] = pb;
    } else {
        float l[7];
        #pragma unroll
        for (int e = 0; e < 7; e++)
            l[e] = pin[e] - __uint_as_float(__float_as_uint(pin[e]) & 0xFFFF0000u);
        uint4 lo;
        lo.x = cvt_bf16x2(l[0], l[1]); lo.y = cvt_bf16x2(l[2], l[3]);
        lo.z = cvt_bf16x2(l[4], l[5]); lo.w = cvt_bf16x2(l[6], 0.f);
        *(uint4*)(smem + OFF_X + slot * 4096 + m * 32 + 16) = lo;
    }
}

// ---------------------------------------------------------------------------
// Persistent fused point kernel.  Per tile: layer1 MMA -> in-register D1->A
// conversion (own k-half) + A16 store (partner half) -> own-half layer2 MMA
// (pre-barrier) -> group barrier -> partner-half layer2 -> segmented max.
// ---------------------------------------------------------------------------
__global__ __launch_bounds__(256, 2) void point_kernel(
    const float* __restrict__ fm,   const int* __restrict__ bidx,
    const float* __restrict__ cond, const float* __restrict__ W1,
    const float* __restrict__ b1,   const float* __restrict__ W2,
    const float* __restrict__ b2,   int N, int numTiles)
{
    extern __shared__ char smem[];
    const uint32_t sbase = smem_u32(smem);
    const int t    = threadIdx.x;
    const int wid  = t >> 5;
    const int lane = t & 31;

    float* b2s = (float*)(smem + OFF_B2);
    int*   bix = (int*)(smem + OFF_BIDX);

    // ---- one-time staging ----
    for (int e = t; e < 4096; e += 256) {          // W2 -> B16 f16 [n][k] SW128
        int n = e >> 5, k2 = e & 31;
        float w0 = W2[(2 * k2) * 128 + n];
        float w1 = W2[(2 * k2 + 1) * 128 + n];
        unsigned off = (unsigned)(n * 128 + k2 * 4);
        *(unsigned*)(smem + OFF_B16 + SWZ(off)) = cvt_f16x2(w0, w1);
    }
    if (t < 64) {                                   // W1 (+bias as k7) bf16 hi/lo
        float w[8];
        #pragma unroll
        for (int k = 0; k < 7; k++) w[k] = W1[k * 64 + t];
        w[7] = b1[t];
        unsigned u[8]; float l[8];
        #pragma unroll
        for (int e = 0; e < 8; e++) {
            u[e] = __float_as_uint(w[e]);
            l[e] = w[e] - __uint_as_float(u[e] & 0xFFFF0000u);
        }
        uint4 hi, lo;
        hi.x = __byte_perm(u[0], u[1], 0x7632);
        hi.y = __byte_perm(u[2], u[3], 0x7632);
        hi.z = __byte_perm(u[4], u[5], 0x7632);
        hi.w = __byte_perm(u[6], u[7], 0x7632);
        lo.x = cvt_bf16x2(l[0], l[1]); lo.y = cvt_bf16x2(l[2], l[3]);
        lo.z = cvt_bf16x2(l[4], l[5]); lo.w = cvt_bf16x2(l[6], l[7]);
        *(uint4*)(smem + OFF_W1A + t * 32)      = hi;
        *(uint4*)(smem + OFF_W1A + t * 32 + 16) = lo;
    }
    if (t < 128) b2s[t] = b2[t];

    const int m    = t & 127;
    const int half = t >> 7;
    const int wm   = wid & 3;      // m 32-slice; group = warps {wm, wm+4}
    const int wn   = wid >> 2;     // n 64-slice (layer2) / k 32-half owner
    const int gbar = 1 + wm;
    const int G    = gridDim.x;

    // ---- prologue: stage tiles it=0 (slot0) and it=1 (slot1); hold it=2 ----
    int tile = blockIdx.x;
    float pin[7]; int pb;
    load_pin(fm, bidx, cond, tile, numTiles, m, N, pin, pb);
    stage_x(smem, 0, m, half, pin, pb);
    load_pin(fm, bidx, cond, tile + G, numTiles, m, N, pin, pb);
    stage_x(smem, 1, m, half, pin, pb);
    load_pin(fm, bidx, cond, tile + 2 * G, numTiles, m, N, pin, pb);
    __syncthreads();   // full barrier: weights + slots 0/1 visible to all

    int it = 0;
    while (tile < numTiles) {
        const int slot = it & 3;
        const uint32_t aoff_base = OFF_A16 + (unsigned)(it & 1) * 16384u;

        // ---- phase 1: layer 1 via bf16-split MMA ----
        unsigned af[2][2][4];   // [mi][j] own-k-half layer-2 A fragments
        {
            unsigned xh[4], xl[4], wh[4], wl[4];
            const uint32_t xaddr = sbase + OFF_X + slot * 4096 + ((wm << 5) + lane) * 32;
            ldsm4(xh, xaddr);
            ldsm4(xl, xaddr + 16);
            const uint32_t waddr = sbase + OFF_W1A + ((wn << 5) + lane) * 32;
            ldsm4(wh, waddr);
            ldsm4(wl, waddr + 16);

            float d1[2][4][4];
            #pragma unroll
            for (int mt = 0; mt < 2; mt++)
                #pragma unroll
                for (int g = 0; g < 4; g++)
                    #pragma unroll
                    for (int e = 0; e < 4; e++) d1[mt][g][e] = 0.f;
            #pragma unroll
            for (int g = 0; g < 4; g++)
                #pragma unroll
                for (int mt = 0; mt < 2; mt++) {
                    hmma_bf8(d1[mt][g], xh[mt * 2], xh[mt * 2 + 1], wh[g]);
                    hmma_bf8(d1[mt][g], xl[mt * 2], xl[mt * 2 + 1], wh[g]);
                    hmma_bf8(d1[mt][g], xh[mt * 2], xh[mt * 2 + 1], wl[g]);
                }
            // in-register conversion: D1 (m16n8) -> A (m16k16) fragments.
            // g pair (2j,2j+1) = kstep (2wn+j).  Same values feed the stores.
            #pragma unroll
            for (int mt = 0; mt < 2; mt++)
                #pragma unroll
                for (int j = 0; j < 2; j++) {
                    af[mt][j][0] = cvt_f16x2(lrelu(d1[mt][2 * j][0]),     lrelu(d1[mt][2 * j][1]));
                    af[mt][j][1] = cvt_f16x2(lrelu(d1[mt][2 * j][2]),     lrelu(d1[mt][2 * j][3]));
                    af[mt][j][2] = cvt_f16x2(lrelu(d1[mt][2 * j + 1][0]), lrelu(d1[mt][2 * j + 1][1]));
                    af[mt][j][3] = cvt_f16x2(lrelu(d1[mt][2 * j + 1][2]), lrelu(d1[mt][2 * j + 1][3]));
                }
            // store to A16 for the partner warp (its missing k-half)
            #pragma unroll
            for (int mt = 0; mt < 2; mt++) {
                const int r0 = (wm << 5) + (mt << 4) + (lane >> 2);
                const int r1 = r0 + 8;
                #pragma unroll
                for (int g = 0; g < 4; g++) {
                    const int c = (wn << 5) + (g << 3) + ((lane & 3) << 1);
                    *(unsigned*)(smem + aoff_base + r0 * 128 +
                                 ((((c >> 3) ^ (r0 & 7)) & 7) << 4) + ((c & 7) << 1)) =
                        af[mt][g >> 1][(g & 1) << 1];
                    *(unsigned*)(smem + aoff_base + r1 * 128 +
                                 ((((c >> 3) ^ (r1 & 7)) & 7) << 4) + ((c & 7) << 1)) =
                        af[mt][g >> 1][((g & 1) << 1) + 1];
                }
            }
        }
        // stage tile it+2 into slot (it+2)&3 from regs loaded last phase 2
        stage_x(smem, (it + 2) & 3, m, half, pin, pb);
        // issue loads for tile it+3 early (hidden behind both GEMM halves)
        load_pin(fm, bidx, cond, tile + 3 * G, numTiles, m, N, pin, pb);

        // ---- phase 2: layer 2 GEMM ----
        float d[2][8][4];
        #pragma unroll
        for (int mi = 0; mi < 2; mi++)
            #pragma unroll
            for (int ni = 0; ni < 8; ni++)
                #pragma unroll
                for (int e = 0; e < 4; e++) d[mi][ni][e] = 0.f;

        const int brow = (wn << 6) + (lane & 7) + ((lane >> 4) << 3);

        // own k-half: A from registers, no barrier needed
        #pragma unroll
        for (int j = 0; j < 2; j++) {
            const int ks = 2 * wn + j;
            int bkch = (ks << 1) + ((lane >> 3) & 1);
            uint32_t boff = (uint32_t)(brow * 128 + (((bkch ^ (brow & 7)) & 7) << 4));
            unsigned bf[4][4];
            #pragma unroll
            for (int g = 0; g < 4; g++) ldsm4(bf[g], sbase + OFF_B16 + boff + g * 2048);
            #pragma unroll
            for (int g = 0; g < 4; g++) {
                #pragma unroll
                for (int mi = 0; mi < 2; mi++) {
                    hmma(d[mi][2 * g + 0], af[mi][j], bf[g][0], bf[g][1]);
                    hmma(d[mi][2 * g + 1], af[mi][j], bf[g][2], bf[g][3]);
                }
            }
        }

        BAR_GROUP(gbar);   // partner's A16 half + X/bix[(it+2)&3] visible

        // partner k-half: A via ldsm from A16
        #pragma unroll
        for (int j = 0; j < 2; j++) {
            const int ks = 2 * (1 - wn) + j;
            int arow = (wm << 5) + (lane & 15);
            int akch = (ks << 1) + (lane >> 4);
            uint32_t aoff = (uint32_t)(arow * 128 + (((akch ^ (arow & 7)) & 7) << 4));
            unsigned ap[2][4];
            ldsm4(ap[0], sbase + aoff_base + aoff);
            ldsm4(ap[1], sbase + aoff_base + aoff + 16 * 128);
            int bkch = (ks << 1) + ((lane >> 3) & 1);
            uint32_t boff = (uint32_t)(brow * 128 + (((bkch ^ (brow & 7)) & 7) << 4));
            unsigned bf[4][4];
            #pragma unroll
            for (int g = 0; g < 4; g++) ldsm4(bf[g], sbase + OFF_B16 + boff + g * 2048);
            #pragma unroll
            for (int g = 0; g < 4; g++) {
                #pragma unroll
                for (int mi = 0; mi < 2; mi++) {
                    hmma(d[mi][2 * g + 0], ap[mi], bf[g][0], bf[g][1]);
                    hmma(d[mi][2 * g + 1], ap[mi], bf[g][2], bf[g][3]);
                }
            }
        }

        // ---- epilogue: in-register segmented max + atomics (per warp) ----
        {
            const int base  = slot * 128 + (wm << 5);
            const int rA    = lane >> 2;
            const int bfirst = bix[base];
            const int blast  = bix[base + 31];
            if (bfirst == blast) {
                float acc[16];
                #pragma unroll
                for (int ni = 0; ni < 8; ni++) {
                    float a0 = fmaxf(fmaxf(d[0][ni][0], d[0][ni][2]),
                                     fmaxf(d[1][ni][0], d[1][ni][2]));
                    float a1 = fmaxf(fmaxf(d[0][ni][1], d[0][ni][3]),
                                     fmaxf(d[1][ni][1], d[1][ni][3]));
                    acc[2 * ni] = a0; acc[2 * ni + 1] = a1;
                }
                #pragma unroll
                for (int q = 0; q < 16; q++) {
                    acc[q] = fmaxf(acc[q], __shfl_xor_sync(0xFFFFFFFFu, acc[q], 4));
                    acc[q] = fmaxf(acc[q], __shfl_xor_sync(0xFFFFFFFFu, acc[q], 8));
                    acc[q] = fmaxf(acc[q], __shfl_xor_sync(0xFFFFFFFFu, acc[q], 16));
                }
                if (lane < 4 && bfirst >= 0) {
                    #pragma unroll
                    for (int ni = 0; ni < 8; ni++) {
                        const int c = (wn << 6) + (ni << 3) + (lane << 1);
                        float y0 = lrelu(acc[2 * ni]     + b2s[c]);
                        float y1 = lrelu(acc[2 * ni + 1] + b2s[c + 1]);
                        atomicMax(&g_gf[(bfirst << 7) + c],     enc_f(y0));
                        atomicMax(&g_gf[(bfirst << 7) + c + 1], enc_f(y1));
                    }
                }
            } else {
                int rstart = 0;
                while (rstart < 32) {
                    const int cur = bix[base + rstart];
                    int rend;
                    if (blast == cur) rend = 32;
                    else {
                        rend = rstart + 1;
                        while (rend < 32 && bix[base + rend] == cur) rend++;
                    }
                    const bool p0 = (rA      >= rstart) && (rA      < rend);
                    const bool p1 = (rA + 8  >= rstart) && (rA + 8  < rend);
                    const bool p2 = (rA + 16 >= rstart) && (rA + 16 < rend);
                    const bool p3 = (rA + 24 >= rstart) && (rA + 24 < rend);
                    float acc[16];
                    #pragma unroll
                    for (int ni = 0; ni < 8; ni++) {
                        float a0 = NEG_INIT, a1 = NEG_INIT;
                        if (p0) { a0 = d[0][ni][0]; a1 = d[0][ni][1]; }
                        if (p1) { a0 = fmaxf(a0, d[0][ni][2]); a1 = fmaxf(a1, d[0][ni][3]); }
                        if (p2) { a0 = fmaxf(a0, d[1][ni][0]); a1 = fmaxf(a1, d[1][ni][1]); }
                        if (p3) { a0 = fmaxf(a0, d[1][ni][2]); a1 = fmaxf(a1, d[1][ni][3]); }
                        acc[2 * ni] = a0; acc[2 * ni + 1] = a1;
                    }
                    #pragma unroll
                    for (int q = 0; q < 16; q++) {
                        acc[q] = fmaxf(acc[q], __shfl_xor_sync(0xFFFFFFFFu, acc[q], 4));
                        acc[q] = fmaxf(acc[q], __shfl_xor_sync(0xFFFFFFFFu, acc[q], 8));
                        acc[q] = fmaxf(acc[q], __shfl_xor_sync(0xFFFFFFFFu, acc[q], 16));
                    }
                    if (lane < 4 && cur >= 0) {
                        #pragma unroll
                        for (int ni = 0; ni < 8; ni++) {
                            const int c = (wn << 6) + (ni << 3) + (lane << 1);
                            float y0 = lrelu(acc[2 * ni]     + b2s[c]);
                            float y1 = lrelu(acc[2 * ni + 1] + b2s[c + 1]);
                            atomicMax(&g_gf[(cur << 7) + c],     enc_f(y0));
                            atomicMax(&g_gf[(cur << 7) + c + 1], enc_f(y1));
                        }
                    }
                    rstart = rend;
                }
            }
        }
        tile += G; it++;
    }
}

// ---------------------------------------------------------------------------
// Decision MLP (unchanged)
// ---------------------------------------------------------------------------
__global__ __launch_bounds__(128) void decision_kernel(
    const float* __restrict__ cond, const float* __restrict__ W3,
    const float* __restrict__ b3,   const float* __restrict__ W4,
    const float* __restrict__ b4,   float* __restrict__ out, int B)
{
    extern __shared__ float sm[];
    float* W3s   = sm;
    float* b3s   = W3s + 16896;
    float* W4s   = b3s + 128;
    float* in_s  = W4s + 128;
    float* hid_s = in_s + 2112;

    const int t = threadIdx.x;
    {
        const float4* src = (const float4*)W3;
        float4* dst = (float4*)W3s;
        for (int i = t; i < 4224; i += 128) dst[i] = src[i];
    }
    b3s[t] = b3[t];
    W4s[t] = W4[t];

    const int b0 = blockIdx.x * 16;
    for (int i = t; i < 16 * 132; i += 128) {
        const int bi = i / 132, k = i % 132, bb = b0 + bi;
        float v = 0.f;
        if (bb < B)
            v = (k < 128) ? dec_f(g_gf[bb * 128 + k]) : cond[bb * 4 + (k - 128)];
        in_s[bi * 132 + k] = v;
    }
    __syncthreads();

    const int j = t;
    for (int i = 0; i < 16; i++) {
        float acc = b3s[j];
        #pragma unroll 4
        for (int k = 0; k < 132; k++) acc += in_s[i * 132 + k] * W3s[k * 128 + j];
        hid_s[i * 128 + j] = lrelu(acc);
    }
    __syncthreads();

    const int i = t >> 3, g = t & 7;
    float acc = 0.f;
    #pragma unroll
    for (int q = 0; q < 16; q++) acc += hid_s[i * 128 + g * 16 + q] * W4s[g * 16 + q];
    acc += __shfl_down_sync(0xFFFFFFFFu, acc, 4, 8);
    acc += __shfl_down_sync(0xFFFFFFFFu, acc, 2, 8);
    acc += __shfl_down_sync(0xFFFFFFFFu, acc, 1, 8);
    if (g == 0 && (b0 + i) < B) out[b0 + i] = acc + b4[0];
}

// ---------------------------------------------------------------------------
extern "C" void kernel_launch(void* const* d_in, const int* in_sizes, int n_in,
                              void* d_out, int out_size)
{
    const float* fm   = (const float*)d_in[0];
    const int*   bi   = (const int*)  d_in[1];
    const float* cond = (const float*)d_in[2];
    const int base = (n_in >= 12) ? 4 : 3;
    const float* W1 = (const float*)d_in[base + 0];
    const float* b1 = (const float*)d_in[base + 1];
    const float* W2 = (const float*)d_in[base + 2];
    const float* b2 = (const float*)d_in[base + 3];
    const float* W3 = (const float*)d_in[base + 4];
    const float* b3 = (const float*)d_in[base + 5];
    const float* W4 = (const float*)d_in[base + 6];
    const float* b4 = (const float*)d_in[base + 7];

    const int N = in_sizes[0] / 3;
    const int B = in_sizes[2] / 4;
    float* out = (float*)d_out;

    cudaFuncSetAttribute(point_kernel,
                         cudaFuncAttributeMaxDynamicSharedMemorySize, SMEM_BYTES);
    const int SMEM_B = 21312 * 4;
    cudaFuncSetAttribute(decision_kernel,
                         cudaFuncAttributeMaxDynamicSharedMemorySize, SMEM_B);

    const int total4 = B * 128 / 4;
    init_gf_kernel<<<(total4 + 255) / 256, 256>>>(total4);

    const int numTiles = (N + 127) / 128;
    point_kernel<<<296, 256, SMEM_BYTES>>>(fm, bi, cond, W1, b1, W2, b2, N, numTiles);

    decision_kernel<<<(B + 15) / 16, 128, SMEM_B>>>(cond, W3, b3, W4, b4, out, B);
}

// round 14
// speedup vs baseline: 2.5138x; 1.1185x over previous
#include <cuda_runtime.h>
#include <cuda_fp16.h>
#include <cstdint>

#define NEG_INIT -1.0e9f

// ---------------------------------------------------------------------------
__device__ __forceinline__ unsigned enc_f(float f) {
    unsigned u = __float_as_uint(f);
    return (u & 0x80000000u) ? ~u : (u | 0x80000000u);
}
__device__ __forceinline__ float dec_f(unsigned e) {
    unsigned u = (e & 0x80000000u) ? (e & 0x7FFFFFFFu) : ~e;
    return __uint_as_float(u);
}
__device__ __forceinline__ float lrelu(float x) { return x >= 0.f ? x : 0.2f * x; }

__device__ unsigned g_gf[16384 * 128];   // encoded global_feats scratch (8 MB)

__device__ __forceinline__ uint32_t smem_u32(const void* p) {
    uint32_t a;
    asm("{ .reg .u64 t; cvta.to.shared.u64 t, %1; cvt.u32.u64 %0, t; }" : "=r"(a) : "l"(p));
    return a;
}

#define SWZ(x) ((x) ^ (((x) >> 3) & 0x70))

// 2-warp (64-thread) named barrier for wm-group: ids 1..4
#define BAR_GROUP(id) asm volatile("bar.sync %0, 64;" :: "r"(id) : "memory")

__device__ __forceinline__ void ldsm4(unsigned r[4], uint32_t addr) {
    asm volatile("ldmatrix.sync.aligned.m8n8.x4.shared.b16 {%0,%1,%2,%3}, [%4];"
                 : "=r"(r[0]), "=r"(r[1]), "=r"(r[2]), "=r"(r[3]) : "r"(addr));
}
// f16 k16 MMA (layer 2)
__device__ __forceinline__ void hmma(float d[4], const unsigned a[4],
                                     unsigned b0, unsigned b1) {
    asm volatile(
        "mma.sync.aligned.m16n8k16.row.col.f32.f16.f16.f32 "
        "{%0,%1,%2,%3}, {%4,%5,%6,%7}, {%8,%9}, {%0,%1,%2,%3};"
        : "+f"(d[0]), "+f"(d[1]), "+f"(d[2]), "+f"(d[3])
        : "r"(a[0]), "r"(a[1]), "r"(a[2]), "r"(a[3]), "r"(b0), "r"(b1));
}
// f16 k8 MMA (layer 1, single product)
__device__ __forceinline__ void hmma_f16k8(float d[4], unsigned a0, unsigned a1,
                                           unsigned b0) {
    asm volatile(
        "mma.sync.aligned.m16n8k8.row.col.f32.f16.f16.f32 "
        "{%0,%1,%2,%3}, {%4,%5}, {%6}, {%0,%1,%2,%3};"
        : "+f"(d[0]), "+f"(d[1]), "+f"(d[2]), "+f"(d[3])
        : "r"(a0), "r"(a1), "r"(b0));
}
__device__ __forceinline__ unsigned cvt_f16x2(float lo, float hi) {
    unsigned r;
    asm("cvt.rn.f16x2.f32 %0, %1, %2;" : "=r"(r) : "f"(hi), "f"(lo));
    return r;
}

// ---------------------------------------------------------------------------
// SMEM layout (bytes)
// ---------------------------------------------------------------------------
#define OFF_B16   0          // [128n][64k] f16, SW128 (W2), 16384 B
#define OFF_A16   16384      // 2 x [128m][64k] f16, SW128 (layer-1 out), 32768 B
#define OFF_X     49152      // 4 x [128m][16B]: f16 k0-6 + k7=1.0
#define OFF_W1A   57344      // [64n][16B]: f16 k0-7 (k7 = b1)
#define OFF_B2    58368      // 128 floats
#define OFF_BIDX  58880      // 4 x 128 ints
#define SMEM_BYTES 60928

// ---------------------------------------------------------------------------
__global__ void init_gf_kernel(int total4) {
    int i = blockIdx.x * blockDim.x + threadIdx.x;
    if (i < total4) {
        unsigned e = enc_f(NEG_INIT);
        ((uint4*)g_gf)[i] = make_uint4(e, e, e, e);
    }
}

// ---------------------------------------------------------------------------
// input load + X staging helpers (half==0 warp of each group only)
// ---------------------------------------------------------------------------
__device__ __forceinline__ void load_pin(
    const float* __restrict__ fm, const int* __restrict__ bidx,
    const float* __restrict__ cond, int tile, int numTiles, int m, int N,
    float pin[7], int& pb)
{
    pb = -1;
    #pragma unroll
    for (int k = 0; k < 7; k++) pin[k] = 0.f;
    if (tile < numTiles) {
        const int row = tile * 128 + m;
        if (row < N) {
            pin[0] = fm[row * 3 + 0]; pin[1] = fm[row * 3 + 1]; pin[2] = fm[row * 3 + 2];
            pb = bidx[row];
            const float4 c4 = *(const float4*)(cond + pb * 4);
            pin[3] = c4.x; pin[4] = c4.y; pin[5] = c4.z; pin[6] = c4.w;
        }
    }
}

__device__ __forceinline__ void stage_x(char* smem, int slot, int m,
                                        const float pin[7], int pb)
{
    uint4 v;
    v.x = cvt_f16x2(pin[0], pin[1]);
    v.y = cvt_f16x2(pin[2], pin[3]);
    v.z = cvt_f16x2(pin[4], pin[5]);
    v.w = cvt_f16x2(pin[6], 1.0f);          // k7 = 1.0 (bias column)
    *(uint4*)(smem + OFF_X + slot * 2048 + m * 16) = v;
    ((int*)(smem + OFF_BIDX))[slot * 128 + m] = pb;
}

// ---------------------------------------------------------------------------
// Persistent fused point kernel.  Per tile: layer1 f16 MMA (1 product) ->
// in-register D1->A conversion (own k-half) + A16 store (partner half) ->
// own-half layer2 MMA (pre-barrier) -> group barrier -> partner-half layer2
// -> in-register segmented max.  4 independent 2-warp pipelines.  grid=296.
// ---------------------------------------------------------------------------
__global__ __launch_bounds__(256, 2) void point_kernel(
    const float* __restrict__ fm,   const int* __restrict__ bidx,
    const float* __restrict__ cond, const float* __restrict__ W1,
    const float* __restrict__ b1,   const float* __restrict__ W2,
    const float* __restrict__ b2,   int N, int numTiles)
{
    extern __shared__ char smem[];
    const uint32_t sbase = smem_u32(smem);
    const int t    = threadIdx.x;
    const int wid  = t >> 5;
    const int lane = t & 31;

    float* b2s = (float*)(smem + OFF_B2);
    int*   bix = (int*)(smem + OFF_BIDX);

    // ---- one-time staging ----
    for (int e = t; e < 4096; e += 256) {          // W2 -> B16 f16 [n][k] SW128
        int n = e >> 5, k2 = e & 31;
        float w0 = W2[(2 * k2) * 128 + n];
        float w1 = W2[(2 * k2 + 1) * 128 + n];
        unsigned off = (unsigned)(n * 128 + k2 * 4);
        *(unsigned*)(smem + OFF_B16 + SWZ(off)) = cvt_f16x2(w0, w1);
    }
    if (t < 64) {                                   // W1 (+bias as k7) f16
        uint4 v;
        v.x = cvt_f16x2(W1[0 * 64 + t], W1[1 * 64 + t]);
        v.y = cvt_f16x2(W1[2 * 64 + t], W1[3 * 64 + t]);
        v.z = cvt_f16x2(W1[4 * 64 + t], W1[5 * 64 + t]);
        v.w = cvt_f16x2(W1[6 * 64 + t], b1[t]);
        *(uint4*)(smem + OFF_W1A + t * 16) = v;
    }
    if (t < 128) b2s[t] = b2[t];

    const int m    = t & 127;
    const int half = t >> 7;
    const int wm   = wid & 3;      // m 32-slice; group = warps {wm, wm+4}
    const int wn   = wid >> 2;     // n 64-slice (layer2) / k 32-half owner
    const int gbar = 1 + wm;
    const int G    = gridDim.x;

    // ---- prologue: stage tiles it=0 (slot0), it=1 (slot1); hold it=2 ----
    int tile = blockIdx.x;
    float pin[7]; int pb = -1;
    if (half == 0) {
        load_pin(fm, bidx, cond, tile, numTiles, m, N, pin, pb);
        stage_x(smem, 0, m, pin, pb);
        load_pin(fm, bidx, cond, tile + G, numTiles, m, N, pin, pb);
        stage_x(smem, 1, m, pin, pb);
        load_pin(fm, bidx, cond, tile + 2 * G, numTiles, m, N, pin, pb);
    }
    __syncthreads();   // full barrier: weights + slots 0/1 visible to all

    int it = 0;
    while (tile < numTiles) {
        const int slot = it & 3;
        const uint32_t aoff_base = OFF_A16 + (unsigned)(it & 1) * 16384u;

        // ---- phase 1: layer 1 f16 MMA (single product) ----
        unsigned af[2][2][4];   // [mi][j] own-k-half layer-2 A fragments
        {
            unsigned xh[4], wh[4];
            ldsm4(xh, sbase + OFF_X + slot * 2048 + ((wm << 5) + lane) * 16);
            ldsm4(wh, sbase + OFF_W1A + ((wn << 5) + lane) * 16);

            float d1[2][4][4];
            #pragma unroll
            for (int mt = 0; mt < 2; mt++)
                #pragma unroll
                for (int g = 0; g < 4; g++)
                    #pragma unroll
                    for (int e = 0; e < 4; e++) d1[mt][g][e] = 0.f;
            #pragma unroll
            for (int g = 0; g < 4; g++)
                #pragma unroll
                for (int mt = 0; mt < 2; mt++)
                    hmma_f16k8(d1[mt][g], xh[mt * 2], xh[mt * 2 + 1], wh[g]);

            // in-register conversion: D1 (m16n8) -> A (m16k16) fragments.
            #pragma unroll
            for (int mt = 0; mt < 2; mt++)
                #pragma unroll
                for (int j = 0; j < 2; j++) {
                    af[mt][j][0] = cvt_f16x2(lrelu(d1[mt][2 * j][0]),     lrelu(d1[mt][2 * j][1]));
                    af[mt][j][1] = cvt_f16x2(lrelu(d1[mt][2 * j][2]),     lrelu(d1[mt][2 * j][3]));
                    af[mt][j][2] = cvt_f16x2(lrelu(d1[mt][2 * j + 1][0]), lrelu(d1[mt][2 * j + 1][1]));
                    af[mt][j][3] = cvt_f16x2(lrelu(d1[mt][2 * j + 1][2]), lrelu(d1[mt][2 * j + 1][3]));
                }
            // store to A16 for the partner warp (its missing k-half)
            #pragma unroll
            for (int mt = 0; mt < 2; mt++) {
                const int r0 = (wm << 5) + (mt << 4) + (lane >> 2);
                const int r1 = r0 + 8;
                #pragma unroll
                for (int g = 0; g < 4; g++) {
                    const int c = (wn << 5) + (g << 3) + ((lane & 3) << 1);
                    *(unsigned*)(smem + aoff_base + r0 * 128 +
                                 ((((c >> 3) ^ (r0 & 7)) & 7) << 4) + ((c & 7) << 1)) =
                        af[mt][g >> 1][(g & 1) << 1];
                    *(unsigned*)(smem + aoff_base + r1 * 128 +
                                 ((((c >> 3) ^ (r1 & 7)) & 7) << 4) + ((c & 7) << 1)) =
                        af[mt][g >> 1][((g & 1) << 1) + 1];
                }
            }
        }
        // stage tile it+2; issue loads for tile it+3 (half==0 warp only)
        if (half == 0) {
            stage_x(smem, (it + 2) & 3, m, pin, pb);
            load_pin(fm, bidx, cond, tile + 3 * G, numTiles, m, N, pin, pb);
        }

        // ---- phase 2: layer 2 GEMM ----
        float d[2][8][4];
        #pragma unroll
        for (int mi = 0; mi < 2; mi++)
            #pragma unroll
            for (int ni = 0; ni < 8; ni++)
                #pragma unroll
                for (int e = 0; e < 4; e++) d[mi][ni][e] = 0.f;

        const int brow = (wn << 6) + (lane & 7) + ((lane >> 4) << 3);

        // own k-half: A from registers, no barrier needed
        #pragma unroll
        for (int j = 0; j < 2; j++) {
            const int ks = 2 * wn + j;
            int bkch = (ks << 1) + ((lane >> 3) & 1);
            uint32_t boff = (uint32_t)(brow * 128 + (((bkch ^ (brow & 7)) & 7) << 4));
            unsigned bf[4][4];
            #pragma unroll
            for (int g = 0; g < 4; g++) ldsm4(bf[g], sbase + OFF_B16 + boff + g * 2048);
            #pragma unroll
            for (int g = 0; g < 4; g++) {
                #pragma unroll
                for (int mi = 0; mi < 2; mi++) {
                    hmma(d[mi][2 * g + 0], af[mi][j], bf[g][0], bf[g][1]);
                    hmma(d[mi][2 * g + 1], af[mi][j], bf[g][2], bf[g][3]);
                }
            }
        }

        BAR_GROUP(gbar);   // partner's A16 half + X/bix[(it+2)&3] visible

        // partner k-half: A via ldsm from A16
        #pragma unroll
        for (int j = 0; j < 2; j++) {
            const int ks = 2 * (1 - wn) + j;
            int arow = (wm << 5) + (lane & 15);
            int akch = (ks << 1) + (lane >> 4);
            uint32_t aoff = (uint32_t)(arow * 128 + (((akch ^ (arow & 7)) & 7) << 4));
            unsigned ap[2][4];
            ldsm4(ap[0], sbase + aoff_base + aoff);
            ldsm4(ap[1], sbase + aoff_base + aoff + 16 * 128);
            int bkch = (ks << 1) + ((lane >> 3) & 1);
            uint32_t boff = (uint32_t)(brow * 128 + (((bkch ^ (brow & 7)) & 7) << 4));
            unsigned bf[4][4];
            #pragma unroll
            for (int g = 0; g < 4; g++) ldsm4(bf[g], sbase + OFF_B16 + boff + g * 2048);
            #pragma unroll
            for (int g = 0; g < 4; g++) {
                #pragma unroll
                for (int mi = 0; mi < 2; mi++) {
                    hmma(d[mi][2 * g + 0], ap[mi], bf[g][0], bf[g][1]);
                    hmma(d[mi][2 * g + 1], ap[mi], bf[g][2], bf[g][3]);
                }
            }
        }

        // ---- epilogue: in-register segmented max + atomics (per warp) ----
        {
            const int base  = slot * 128 + (wm << 5);
            const int rA    = lane >> 2;
            const int bfirst = bix[base];
            const int blast  = bix[base + 31];
            if (bfirst == blast) {
                float acc[16];
                #pragma unroll
                for (int ni = 0; ni < 8; ni++) {
                    float a0 = fmaxf(fmaxf(d[0][ni][0], d[0][ni][2]),
                                     fmaxf(d[1][ni][0], d[1][ni][2]));
                    float a1 = fmaxf(fmaxf(d[0][ni][1], d[0][ni][3]),
                                     fmaxf(d[1][ni][1], d[1][ni][3]));
                    acc[2 * ni] = a0; acc[2 * ni + 1] = a1;
                }
                #pragma unroll
                for (int q = 0; q < 16; q++) {
                    acc[q] = fmaxf(acc[q], __shfl_xor_sync(0xFFFFFFFFu, acc[q], 4));
                    acc[q] = fmaxf(acc[q], __shfl_xor_sync(0xFFFFFFFFu, acc[q], 8));
                    acc[q] = fmaxf(acc[q], __shfl_xor_sync(0xFFFFFFFFu, acc[q], 16));
                }
                if (lane < 4 && bfirst >= 0) {
                    #pragma unroll
                    for (int ni = 0; ni < 8; ni++) {
                        const int c = (wn << 6) + (ni << 3) + (lane << 1);
                        float y0 = lrelu(acc[2 * ni]     + b2s[c]);
                        float y1 = lrelu(acc[2 * ni + 1] + b2s[c + 1]);
                        atomicMax(&g_gf[(bfirst << 7) + c],     enc_f(y0));
                        atomicMax(&g_gf[(bfirst << 7) + c + 1], enc_f(y1));
                    }
                }
            } else {
                int rstart = 0;
                while (rstart < 32) {
                    const int cur = bix[base + rstart];
                    int rend;
                    if (blast == cur) rend = 32;
                    else {
                        rend = rstart + 1;
                        while (rend < 32 && bix[base + rend] == cur) rend++;
                    }
                    const bool p0 = (rA      >= rstart) && (rA      < rend);
                    const bool p1 = (rA + 8  >= rstart) && (rA + 8  < rend);
                    const bool p2 = (rA + 16 >= rstart) && (rA + 16 < rend);
                    const bool p3 = (rA + 24 >= rstart) && (rA + 24 < rend);
                    float acc[16];
                    #pragma unroll
                    for (int ni = 0; ni < 8; ni++) {
                        float a0 = NEG_INIT, a1 = NEG_INIT;
                        if (p0) { a0 = d[0][ni][0]; a1 = d[0][ni][1]; }
                        if (p1) { a0 = fmaxf(a0, d[0][ni][2]); a1 = fmaxf(a1, d[0][ni][3]); }
                        if (p2) { a0 = fmaxf(a0, d[1][ni][0]); a1 = fmaxf(a1, d[1][ni][1]); }
                        if (p3) { a0 = fmaxf(a0, d[1][ni][2]); a1 = fmaxf(a1, d[1][ni][3]); }
                        acc[2 * ni] = a0; acc[2 * ni + 1] = a1;
                    }
                    #pragma unroll
                    for (int q = 0; q < 16; q++) {
                        acc[q] = fmaxf(acc[q], __shfl_xor_sync(0xFFFFFFFFu, acc[q], 4));
                        acc[q] = fmaxf(acc[q], __shfl_xor_sync(0xFFFFFFFFu, acc[q], 8));
                        acc[q] = fmaxf(acc[q], __shfl_xor_sync(0xFFFFFFFFu, acc[q], 16));
                    }
                    if (lane < 4 && cur >= 0) {
                        #pragma unroll
                        for (int ni = 0; ni < 8; ni++) {
                            const int c = (wn << 6) + (ni << 3) + (lane << 1);
                            float y0 = lrelu(acc[2 * ni]     + b2s[c]);
                            float y1 = lrelu(acc[2 * ni + 1] + b2s[c + 1]);
                            atomicMax(&g_gf[(cur << 7) + c],     enc_f(y0));
                            atomicMax(&g_gf[(cur << 7) + c + 1], enc_f(y1));
                        }
                    }
                    rstart = rend;
                }
            }
        }
        tile += G; it++;
    }
}

// ---------------------------------------------------------------------------
// Decision MLP (unchanged)
// ---------------------------------------------------------------------------
__global__ __launch_bounds__(128) void decision_kernel(
    const float* __restrict__ cond, const float* __restrict__ W3,
    const float* __restrict__ b3,   const float* __restrict__ W4,
    const float* __restrict__ b4,   float* __restrict__ out, int B)
{
    extern __shared__ float sm[];
    float* W3s   = sm;
    float* b3s   = W3s + 16896;
    float* W4s   = b3s + 128;
    float* in_s  = W4s + 128;
    float* hid_s = in_s + 2112;

    const int t = threadIdx.x;
    {
        const float4* src = (const float4*)W3;
        float4* dst = (float4*)W3s;
        for (int i = t; i < 4224; i += 128) dst[i] = src[i];
    }
    b3s[t] = b3[t];
    W4s[t] = W4[t];

    const int b0 = blockIdx.x * 16;
    for (int i = t; i < 16 * 132; i += 128) {
        const int bi = i / 132, k = i % 132, bb = b0 + bi;
        float v = 0.f;
        if (bb < B)
            v = (k < 128) ? dec_f(g_gf[bb * 128 + k]) : cond[bb * 4 + (k - 128)];
        in_s[bi * 132 + k] = v;
    }
    __syncthreads();

    const int j = t;
    for (int i = 0; i < 16; i++) {
        float acc = b3s[j];
        #pragma unroll 4
        for (int k = 0; k < 132; k++) acc += in_s[i * 132 + k] * W3s[k * 128 + j];
        hid_s[i * 128 + j] = lrelu(acc);
    }
    __syncthreads();

    const int i = t >> 3, g = t & 7;
    float acc = 0.f;
    #pragma unroll
    for (int q = 0; q < 16; q++) acc += hid_s[i * 128 + g * 16 + q] * W4s[g * 16 + q];
    acc += __shfl_down_sync(0xFFFFFFFFu, acc, 4, 8);
    acc += __shfl_down_sync(0xFFFFFFFFu, acc, 2, 8);
    acc += __shfl_down_sync(0xFFFFFFFFu, acc, 1, 8);
    if (g == 0 && (b0 + i) < B) out[b0 + i] = acc + b4[0];
}

// ---------------------------------------------------------------------------
extern "C" void kernel_launch(void* const* d_in, const int* in_sizes, int n_in,
                              void* d_out, int out_size)
{
    const float* fm   = (const float*)d_in[0];
    const int*   bi   = (const int*)  d_in[1];
    const float* cond = (const float*)d_in[2];
    const int base = (n_in >= 12) ? 4 : 3;
    const float* W1 = (const float*)d_in[base + 0];
    const float* b1 = (const float*)d_in[base + 1];
    const float* W2 = (const float*)d_in[base + 2];
    const float* b2 = (const float*)d_in[base + 3];
    const float* W3 = (const float*)d_in[base + 4];
    const float* b3 = (const float*)d_in[base + 5];
    const float* W4 = (const float*)d_in[base + 6];
    const float* b4 = (const float*)d_in[base + 7];

    const int N = in_sizes[0] / 3;
    const int B = in_sizes[2] / 4;
    float* out = (float*)d_out;

    cudaFuncSetAttribute(point_kernel,
                         cudaFuncAttributeMaxDynamicSharedMemorySize, SMEM_BYTES);
    const int SMEM_B = 21312 * 4;
    cudaFuncSetAttribute(decision_kernel,
                         cudaFuncAttributeMaxDynamicSharedMemorySize, SMEM_B);

    const int total4 = B * 128 / 4;
    init_gf_kernel<<<(total4 + 255) / 256, 256>>>(total4);

    const int numTiles = (N + 127) / 128;
    point_kernel<<<296, 256, SMEM_BYTES>>>(fm, bi, cond, W1, b1, W2, b2, N, numTiles);

    decision_kernel<<<(B + 15) / 16, 128, SMEM_B>>>(cond, W3, b3, W4, b4, out, B);
}

// round 16
// speedup vs baseline: 2.5487x; 1.0139x over previous
#include <cuda_runtime.h>
#include <cuda_fp16.h>
#include <cstdint>

#define NEG_INIT -1.0e9f

// ---------------------------------------------------------------------------
__device__ __forceinline__ unsigned enc_f(float f) {
    unsigned u = __float_as_uint(f);
    return (u & 0x80000000u) ? ~u : (u | 0x80000000u);
}
__device__ __forceinline__ float dec_f(unsigned e) {
    unsigned u = (e & 0x80000000u) ? (e & 0x7FFFFFFFu) : ~e;
    return __uint_as_float(u);
}
__device__ __forceinline__ float lrelu(float x) { return x >= 0.f ? x : 0.2f * x; }

__device__ unsigned g_gf[16384 * 128];   // encoded global_feats scratch (8 MB)

__device__ __forceinline__ uint32_t smem_u32(const void* p) {
    uint32_t a;
    asm("{ .reg .u64 t; cvta.to.shared.u64 t, %1; cvt.u32.u64 %0, t; }" : "=r"(a) : "l"(p));
    return a;
}

#define SWZ(x) ((x) ^ (((x) >> 3) & 0x70))

// 2-warp (64-thread) named barrier for wm-group: ids 1..4
#define BAR_GROUP(id) asm volatile("bar.sync %0, 64;" :: "r"(id) : "memory")

__device__ __forceinline__ void ldsm4(unsigned r[4], uint32_t addr) {
    asm volatile("ldmatrix.sync.aligned.m8n8.x4.shared.b16 {%0,%1,%2,%3}, [%4];"
                 : "=r"(r[0]), "=r"(r[1]), "=r"(r[2]), "=r"(r[3]) : "r"(addr));
}
// f16 k16 MMA (layer 2)
__device__ __forceinline__ void hmma(float d[4], const unsigned a[4],
                                     unsigned b0, unsigned b1) {
    asm volatile(
        "mma.sync.aligned.m16n8k16.row.col.f32.f16.f16.f32 "
        "{%0,%1,%2,%3}, {%4,%5,%6,%7}, {%8,%9}, {%0,%1,%2,%3};"
        : "+f"(d[0]), "+f"(d[1]), "+f"(d[2]), "+f"(d[3])
        : "r"(a[0]), "r"(a[1]), "r"(a[2]), "r"(a[3]), "r"(b0), "r"(b1));
}
// f16 k8 MMA (layer 1, single product)
__device__ __forceinline__ void hmma_f16k8(float d[4], unsigned a0, unsigned a1,
                                           unsigned b0) {
    asm volatile(
        "mma.sync.aligned.m16n8k8.row.col.f32.f16.f16.f32 "
        "{%0,%1,%2,%3}, {%4,%5}, {%6}, {%0,%1,%2,%3};"
        : "+f"(d[0]), "+f"(d[1]), "+f"(d[2]), "+f"(d[3])
        : "r"(a0), "r"(a1), "r"(b0));
}
__device__ __forceinline__ unsigned cvt_f16x2(float lo, float hi) {
    unsigned r;
    asm("cvt.rn.f16x2.f32 %0, %1, %2;" : "=r"(r) : "f"(hi), "f"(lo));
    return r;
}

// ---------------------------------------------------------------------------
// SMEM layout (bytes) - point kernel
// ---------------------------------------------------------------------------
#define OFF_B16   0          // [128n][64k] f16, SW128 (W2), 16384 B
#define OFF_A16   16384      // 2 x [128m][64k] f16, SW128 (layer-1 out), 32768 B
#define OFF_X     49152      // 4 x [128m][16B]: f16 k0-6 + k7=1.0
#define OFF_W1A   57344      // [64n][16B]: f16 k0-7 (k7 = b1)
#define OFF_B2    58368      // 128 floats
#define OFF_BIDX  58880      // 4 x 128 ints
#define SMEM_BYTES 60928

// ---------------------------------------------------------------------------
__global__ void init_gf_kernel(int total4) {
    int i = blockIdx.x * blockDim.x + threadIdx.x;
    if (i < total4) {
        unsigned e = enc_f(NEG_INIT);
        ((uint4*)g_gf)[i] = make_uint4(e, e, e, e);
    }
}

// ---------------------------------------------------------------------------
// input load + X staging helpers (half==0 warp of each group only)
// ---------------------------------------------------------------------------
__device__ __forceinline__ void load_pin(
    const float* __restrict__ fm, const int* __restrict__ bidx,
    const float* __restrict__ cond, int tile, int numTiles, int m, int N,
    float pin[7], int& pb)
{
    pb = -1;
    #pragma unroll
    for (int k = 0; k < 7; k++) pin[k] = 0.f;
    if (tile < numTiles) {
        const int row = tile * 128 + m;
        if (row < N) {
            pin[0] = fm[row * 3 + 0]; pin[1] = fm[row * 3 + 1]; pin[2] = fm[row * 3 + 2];
            pb = bidx[row];
            const float4 c4 = *(const float4*)(cond + pb * 4);
            pin[3] = c4.x; pin[4] = c4.y; pin[5] = c4.z; pin[6] = c4.w;
        }
    }
}

__device__ __forceinline__ void stage_x(char* smem, int slot, int m,
                                        const float pin[7], int pb)
{
    uint4 v;
    v.x = cvt_f16x2(pin[0], pin[1]);
    v.y = cvt_f16x2(pin[2], pin[3]);
    v.z = cvt_f16x2(pin[4], pin[5]);
    v.w = cvt_f16x2(pin[6], 1.0f);          // k7 = 1.0 (bias column)
    *(uint4*)(smem + OFF_X + slot * 2048 + m * 16) = v;
    ((int*)(smem + OFF_BIDX))[slot * 128 + m] = pb;
}

// ---------------------------------------------------------------------------
// Persistent fused point kernel (unchanged from round 14 - at mma roofline)
// ---------------------------------------------------------------------------
__global__ __launch_bounds__(256, 2) void point_kernel(
    const float* __restrict__ fm,   const int* __restrict__ bidx,
    const float* __restrict__ cond, const float* __restrict__ W1,
    const float* __restrict__ b1,   const float* __restrict__ W2,
    const float* __restrict__ b2,   int N, int numTiles)
{
    extern __shared__ char smem[];
    const uint32_t sbase = smem_u32(smem);
    const int t    = threadIdx.x;
    const int wid  = t >> 5;
    const int lane = t & 31;

    float* b2s = (float*)(smem + OFF_B2);
    int*   bix = (int*)(smem + OFF_BIDX);

    for (int e = t; e < 4096; e += 256) {          // W2 -> B16 f16 [n][k] SW128
        int n = e >> 5, k2 = e & 31;
        float w0 = W2[(2 * k2) * 128 + n];
        float w1 = W2[(2 * k2 + 1) * 128 + n];
        unsigned off = (unsigned)(n * 128 + k2 * 4);
        *(unsigned*)(smem + OFF_B16 + SWZ(off)) = cvt_f16x2(w0, w1);
    }
    if (t < 64) {                                   // W1 (+bias as k7) f16
        uint4 v;
        v.x = cvt_f16x2(W1[0 * 64 + t], W1[1 * 64 + t]);
        v.y = cvt_f16x2(W1[2 * 64 + t], W1[3 * 64 + t]);
        v.z = cvt_f16x2(W1[4 * 64 + t], W1[5 * 64 + t]);
        v.w = cvt_f16x2(W1[6 * 64 + t], b1[t]);
        *(uint4*)(smem + OFF_W1A + t * 16) = v;
    }
    if (t < 128) b2s[t] = b2[t];

    const int m    = t & 127;
    const int half = t >> 7;
    const int wm   = wid & 3;
    const int wn   = wid >> 2;
    const int gbar = 1 + wm;
    const int G    = gridDim.x;

    int tile = blockIdx.x;
    float pin[7]; int pb = -1;
    if (half == 0) {
        load_pin(fm, bidx, cond, tile, numTiles, m, N, pin, pb);
        stage_x(smem, 0, m, pin, pb);
        load_pin(fm, bidx, cond, tile + G, numTiles, m, N, pin, pb);
        stage_x(smem, 1, m, pin, pb);
        load_pin(fm, bidx, cond, tile + 2 * G, numTiles, m, N, pin, pb);
    }
    __syncthreads();

    int it = 0;
    while (tile < numTiles) {
        const int slot = it & 3;
        const uint32_t aoff_base = OFF_A16 + (unsigned)(it & 1) * 16384u;

        unsigned af[2][2][4];
        {
            unsigned xh[4], wh[4];
            ldsm4(xh, sbase + OFF_X + slot * 2048 + ((wm << 5) + lane) * 16);
            ldsm4(wh, sbase + OFF_W1A + ((wn << 5) + lane) * 16);

            float d1[2][4][4];
            #pragma unroll
            for (int mt = 0; mt < 2; mt++)
                #pragma unroll
                for (int g = 0; g < 4; g++)
                    #pragma unroll
                    for (int e = 0; e < 4; e++) d1[mt][g][e] = 0.f;
            #pragma unroll
            for (int g = 0; g < 4; g++)
                #pragma unroll
                for (int mt = 0; mt < 2; mt++)
                    hmma_f16k8(d1[mt][g], xh[mt * 2], xh[mt * 2 + 1], wh[g]);

            #pragma unroll
            for (int mt = 0; mt < 2; mt++)
                #pragma unroll
                for (int j = 0; j < 2; j++) {
                    af[mt][j][0] = cvt_f16x2(lrelu(d1[mt][2 * j][0]),     lrelu(d1[mt][2 * j][1]));
                    af[mt][j][1] = cvt_f16x2(lrelu(d1[mt][2 * j][2]),     lrelu(d1[mt][2 * j][3]));
                    af[mt][j][2] = cvt_f16x2(lrelu(d1[mt][2 * j + 1][0]), lrelu(d1[mt][2 * j + 1][1]));
                    af[mt][j][3] = cvt_f16x2(lrelu(d1[mt][2 * j + 1][2]), lrelu(d1[mt][2 * j + 1][3]));
                }
            #pragma unroll
            for (int mt = 0; mt < 2; mt++) {
                const int r0 = (wm << 5) + (mt << 4) + (lane >> 2);
                const int r1 = r0 + 8;
                #pragma unroll
                for (int g = 0; g < 4; g++) {
                    const int c = (wn << 5) + (g << 3) + ((lane & 3) << 1);
                    *(unsigned*)(smem + aoff_base + r0 * 128 +
                                 ((((c >> 3) ^ (r0 & 7)) & 7) << 4) + ((c & 7) << 1)) =
                        af[mt][g >> 1][(g & 1) << 1];
                    *(unsigned*)(smem + aoff_base + r1 * 128 +
                                 ((((c >> 3) ^ (r1 & 7)) & 7) << 4) + ((c & 7) << 1)) =
                        af[mt][g >> 1][((g & 1) << 1) + 1];
                }
            }
        }
        if (half == 0) {
            stage_x(smem, (it + 2) & 3, m, pin, pb);
            load_pin(fm, bidx, cond, tile + 3 * G, numTiles, m, N, pin, pb);
        }

        float d[2][8][4];
        #pragma unroll
        for (int mi = 0; mi < 2; mi++)
            #pragma unroll
            for (int ni = 0; ni < 8; ni++)
                #pragma unroll
                for (int e = 0; e < 4; e++) d[mi][ni][e] = 0.f;

        const int brow = (wn << 6) + (lane & 7) + ((lane >> 4) << 3);

        #pragma unroll
        for (int j = 0; j < 2; j++) {
            const int ks = 2 * wn + j;
            int bkch = (ks << 1) + ((lane >> 3) & 1);
            uint32_t boff = (uint32_t)(brow * 128 + (((bkch ^ (brow & 7)) & 7) << 4));
            unsigned bf[4][4];
            #pragma unroll
            for (int g = 0; g < 4; g++) ldsm4(bf[g], sbase + OFF_B16 + boff + g * 2048);
            #pragma unroll
            for (int g = 0; g < 4; g++) {
                #pragma unroll
                for (int mi = 0; mi < 2; mi++) {
                    hmma(d[mi][2 * g + 0], af[mi][j], bf[g][0], bf[g][1]);
                    hmma(d[mi][2 * g + 1], af[mi][j], bf[g][2], bf[g][3]);
                }
            }
        }

        BAR_GROUP(gbar);

        #pragma unroll
        for (int j = 0; j < 2; j++) {
            const int ks = 2 * (1 - wn) + j;
            int arow = (wm << 5) + (lane & 15);
            int akch = (ks << 1) + (lane >> 4);
            uint32_t aoff = (uint32_t)(arow * 128 + (((akch ^ (arow & 7)) & 7) << 4));
            unsigned ap[2][4];
            ldsm4(ap[0], sbase + aoff_base + aoff);
            ldsm4(ap[1], sbase + aoff_base + aoff + 16 * 128);
            int bkch = (ks << 1) + ((lane >> 3) & 1);
            uint32_t boff = (uint32_t)(brow * 128 + (((bkch ^ (brow & 7)) & 7) << 4));
            unsigned bf[4][4];
            #pragma unroll
            for (int g = 0; g < 4; g++) ldsm4(bf[g], sbase + OFF_B16 + boff + g * 2048);
            #pragma unroll
            for (int g = 0; g < 4; g++) {
                #pragma unroll
                for (int mi = 0; mi < 2; mi++) {
                    hmma(d[mi][2 * g + 0], ap[mi], bf[g][0], bf[g][1]);
                    hmma(d[mi][2 * g + 1], ap[mi], bf[g][2], bf[g][3]);
                }
            }
        }

        {
            const int base  = slot * 128 + (wm << 5);
            const int rA    = lane >> 2;
            const int bfirst = bix[base];
            const int blast  = bix[base + 31];
            if (bfirst == blast) {
                float acc[16];
                #pragma unroll
                for (int ni = 0; ni < 8; ni++) {
                    float a0 = fmaxf(fmaxf(d[0][ni][0], d[0][ni][2]),
                                     fmaxf(d[1][ni][0], d[1][ni][2]));
                    float a1 = fmaxf(fmaxf(d[0][ni][1], d[0][ni][3]),
                                     fmaxf(d[1][ni][1], d[1][ni][3]));
                    acc[2 * ni] = a0; acc[2 * ni + 1] = a1;
                }
                #pragma unroll
                for (int q = 0; q < 16; q++) {
                    acc[q] = fmaxf(acc[q], __shfl_xor_sync(0xFFFFFFFFu, acc[q], 4));
                    acc[q] = fmaxf(acc[q], __shfl_xor_sync(0xFFFFFFFFu, acc[q], 8));
                    acc[q] = fmaxf(acc[q], __shfl_xor_sync(0xFFFFFFFFu, acc[q], 16));
                }
                if (lane < 4 && bfirst >= 0) {
                    #pragma unroll
                    for (int ni = 0; ni < 8; ni++) {
                        const int c = (wn << 6) + (ni << 3) + (lane << 1);
                        float y0 = lrelu(acc[2 * ni]     + b2s[c]);
                        float y1 = lrelu(acc[2 * ni + 1] + b2s[c + 1]);
                        atomicMax(&g_gf[(bfirst << 7) + c],     enc_f(y0));
                        atomicMax(&g_gf[(bfirst << 7) + c + 1], enc_f(y1));
                    }
                }
            } else {
                int rstart = 0;
                while (rstart < 32) {
                    const int cur = bix[base + rstart];
                    int rend;
                    if (blast == cur) rend = 32;
                    else {
                        rend = rstart + 1;
                        while (rend < 32 && bix[base + rend] == cur) rend++;
                    }
                    const bool p0 = (rA      >= rstart) && (rA      < rend);
                    const bool p1 = (rA + 8  >= rstart) && (rA + 8  < rend);
                    const bool p2 = (rA + 16 >= rstart) && (rA + 16 < rend);
                    const bool p3 = (rA + 24 >= rstart) && (rA + 24 < rend);
                    float acc[16];
                    #pragma unroll
                    for (int ni = 0; ni < 8; ni++) {
                        float a0 = NEG_INIT, a1 = NEG_INIT;
                        if (p0) { a0 = d[0][ni][0]; a1 = d[0][ni][1]; }
                        if (p1) { a0 = fmaxf(a0, d[0][ni][2]); a1 = fmaxf(a1, d[0][ni][3]); }
                        if (p2) { a0 = fmaxf(a0, d[1][ni][0]); a1 = fmaxf(a1, d[1][ni][1]); }
                        if (p3) { a0 = fmaxf(a0, d[1][ni][2]); a1 = fmaxf(a1, d[1][ni][3]); }
                        acc[2 * ni] = a0; acc[2 * ni + 1] = a1;
                    }
                    #pragma unroll
                    for (int q = 0; q < 16; q++) {
                        acc[q] = fmaxf(acc[q], __shfl_xor_sync(0xFFFFFFFFu, acc[q], 4));
                        acc[q] = fmaxf(acc[q], __shfl_xor_sync(0xFFFFFFFFu, acc[q], 8));
                        acc[q] = fmaxf(acc[q], __shfl_xor_sync(0xFFFFFFFFu, acc[q], 16));
                    }
                    if (lane < 4 && cur >= 0) {
                        #pragma unroll
                        for (int ni = 0; ni < 8; ni++) {
                            const int c = (wn << 6) + (ni << 3) + (lane << 1);
                            float y0 = lrelu(acc[2 * ni]     + b2s[c]);
                            float y1 = lrelu(acc[2 * ni + 1] + b2s[c + 1]);
                            atomicMax(&g_gf[(cur << 7) + c],     enc_f(y0));
                            atomicMax(&g_gf[(cur << 7) + c + 1], enc_f(y1));
                        }
                    }
                    rstart = rend;
                }
            }
        }
        tile += G; it++;
    }
}

// ---------------------------------------------------------------------------
// Decision MLP, restructured: 32 batches/block, k-outer + 32-batch register
// accumulators, float4 in_s reads.  128 threads (j = t).  hid overlays in_s.
// smem floats: W3s 16896 | b3s 128 | W4s 128 | union{in_s 32*132, hid 32*128}
// ---------------------------------------------------------------------------
#define DK_SMEM_FLOATS (16896 + 128 + 128 + 4224)
__global__ __launch_bounds__(128) void decision_kernel(
    const float* __restrict__ cond, const float* __restrict__ W3,
    const float* __restrict__ b3,   const float* __restrict__ W4,
    const float* __restrict__ b4,   float* __restrict__ out, int B)
{
    extern __shared__ float sm[];
    float* W3s   = sm;
    float* b3s   = W3s + 16896;
    float* W4s   = b3s + 128;
    float* in_s  = W4s + 128;     // 32*132 floats (rows 16B-aligned: 528 B)
    float* hid_s = in_s;          // overlay after barrier: 32*128 floats

    const int t = threadIdx.x;
    {
        const float4* src = (const float4*)W3;
        float4* dst = (float4*)W3s;
        #pragma unroll 4
        for (int i = t; i < 4224; i += 128) dst[i] = src[i];
    }
    b3s[t] = b3[t];
    W4s[t] = W4[t];

    const int b0 = blockIdx.x * 32;
    for (int i = t; i < 32 * 132; i += 128) {
        const int bi = i / 132, k = i % 132, bb = b0 + bi;
        float v = 0.f;
        if (bb < B)
            v = (k < 128) ? dec_f(g_gf[bb * 128 + k]) : cond[bb * 4 + (k - 128)];
        in_s[bi * 132 + k] = v;
    }
    __syncthreads();

    // hidden unit j = t, 32 batches in registers; k vectorized by 4
    const int j = t;
    float acc[32];
    #pragma unroll
    for (int i = 0; i < 32; i++) acc[i] = b3s[j];
    for (int k4 = 0; k4 < 33; k4++) {
        const float w0 = W3s[(4 * k4 + 0) * 128 + j];
        const float w1 = W3s[(4 * k4 + 1) * 128 + j];
        const float w2 = W3s[(4 * k4 + 2) * 128 + j];
        const float w3 = W3s[(4 * k4 + 3) * 128 + j];
        #pragma unroll 8
        for (int i = 0; i < 32; i++) {
            const float4 v = *(const float4*)(in_s + i * 132 + 4 * k4);
            acc[i] += v.x * w0 + v.y * w1 + v.z * w2 + v.w * w3;
        }
    }
    __syncthreads();   // all in_s reads done before hid overlay

    #pragma unroll
    for (int i = 0; i < 32; i++) hid_s[i * 128 + j] = lrelu(acc[i]);
    __syncthreads();

    // final dot with W4: 4 threads cooperate per batch (i = t>>2, g = t&3)
    const int i = t >> 2, g = t & 3;
    float s = 0.f;
    #pragma unroll
    for (int q = 0; q < 32; q++) s += hid_s[i * 128 + g * 32 + q] * W4s[g * 32 + q];
    s += __shfl_down_sync(0xFFFFFFFFu, s, 2, 4);
    s += __shfl_down_sync(0xFFFFFFFFu, s, 1, 4);
    if (g == 0 && (b0 + i) < B) out[b0 + i] = s + b4[0];
}

// ---------------------------------------------------------------------------
extern "C" void kernel_launch(void* const* d_in, const int* in_sizes, int n_in,
                              void* d_out, int out_size)
{
    const float* fm   = (const float*)d_in[0];
    const int*   bi   = (const int*)  d_in[1];
    const float* cond = (const float*)d_in[2];
    const int base = (n_in >= 12) ? 4 : 3;
    const float* W1 = (const float*)d_in[base + 0];
    const float* b1 = (const float*)d_in[base + 1];
    const float* W2 = (const float*)d_in[base + 2];
    const float* b2 = (const float*)d_in[base + 3];
    const float* W3 = (const float*)d_in[base + 4];
    const float* b3 = (const float*)d_in[base + 5];
    const float* W4 = (const float*)d_in[base + 6];
    const float* b4 = (const float*)d_in[base + 7];

    const int N = in_sizes[0] / 3;
    const int B = in_sizes[2] / 4;
    float* out = (float*)d_out;

    cudaFuncSetAttribute(point_kernel,
                         cudaFuncAttributeMaxDynamicSharedMemorySize, SMEM_BYTES);
    const int SMEM_B = DK_SMEM_FLOATS * 4;
    cudaFuncSetAttribute(decision_kernel,
                         cudaFuncAttributeMaxDynamicSharedMemorySize, SMEM_B);

    const int total4 = B * 128 / 4;
    init_gf_kernel<<<(total4 + 255) / 256, 256>>>(total4);

    const int numTiles = (N + 127) / 128;
    point_kernel<<<296, 256, SMEM_BYTES>>>(fm, bi, cond, W1, b1, W2, b2, N, numTiles);

    decision_kernel<<<(B + 31) / 32, 128, SMEM_B>>>(cond, W3, b3, W4, b4, out, B);
}